// round 1
// baseline (speedup 1.0000x reference)
#include <cuda_runtime.h>
#include <math.h>
#include <stddef.h>

// Problem constants
#define BB 4
#define CC 256
#define NN 4096

// Scratch (allocation-free rule: __device__ globals)
__device__ float g_q[BB * CC * NN];
__device__ float g_k[BB * CC * NN];
__device__ float g_v[BB * CC * NN];
__device__ float g_s[(size_t)BB * NN * NN];   // 256 MB scores/attn
__device__ float g_av[BB * CC * NN];
__device__ float g_h[BB * CC * NN];

// ---------------------------------------------------------------------------
// Generic projection GEMM: out[b][o][n] = sum_c W[o][c] * X[b][c][n] + bias[o]
// W: [CC, CC] row-major (c fast). X: [BB, CC, NN] (n fast).
// 64x64 output tile, K-step 16, 256 threads, 4x4 per thread.
// ---------------------------------------------------------------------------
template <bool RELU>
__global__ void gemm_wx(const float* __restrict__ W,
                        const float* __restrict__ X,
                        const float* __restrict__ bias,
                        float* __restrict__ out) {
    __shared__ float Ws[16][68];  // [k][o]
    __shared__ float Xs[16][68];  // [k][n]

    const int b  = blockIdx.z;
    const int o0 = blockIdx.y * 64;
    const int n0 = blockIdx.x * 64;
    const float* Xb = X + (size_t)b * CC * NN;
    float* Ob       = out + (size_t)b * CC * NN;

    const int tid = threadIdx.x;       // 0..255
    const int tx  = tid & 15;
    const int ty  = tid >> 4;

    float acc[4][4] = {};

    for (int k0 = 0; k0 < CC; k0 += 16) {
        // W tile [64 o][16 k] -> transposed Ws[k][o]
#pragma unroll
        for (int p = 0; p < 4; p++) {
            int idx = tid + p * 256;
            int r = idx >> 4, c = idx & 15;
            Ws[c][r] = W[(size_t)(o0 + r) * CC + (k0 + c)];
        }
        // X tile [16 k][64 n]
#pragma unroll
        for (int p = 0; p < 4; p++) {
            int idx = tid + p * 256;
            int r = idx >> 6, c = idx & 63;
            Xs[r][c] = Xb[(size_t)(k0 + r) * NN + (n0 + c)];
        }
        __syncthreads();
#pragma unroll
        for (int kk = 0; kk < 16; kk++) {
            float4 a4 = *(const float4*)&Ws[kk][ty * 4];
            float4 b4 = *(const float4*)&Xs[kk][tx * 4];
            float a[4] = {a4.x, a4.y, a4.z, a4.w};
            float bb[4] = {b4.x, b4.y, b4.z, b4.w};
#pragma unroll
            for (int i = 0; i < 4; i++)
#pragma unroll
                for (int j = 0; j < 4; j++) acc[i][j] = fmaf(a[i], bb[j], acc[i][j]);
        }
        __syncthreads();
    }

#pragma unroll
    for (int i = 0; i < 4; i++) {
        int o = o0 + ty * 4 + i;
        float bs = bias[o];
#pragma unroll
        for (int j = 0; j < 4; j++) {
            float v = acc[i][j] + bs;
            if (RELU) v = fmaxf(v, 0.0f);
            Ob[(size_t)o * NN + (n0 + tx * 4 + j)] = v;
        }
    }
}

// ---------------------------------------------------------------------------
// Scores: S[b][n][m] = sum_c q[b][c][n] * k[b][c][m]   (TN: K slow in both)
// ---------------------------------------------------------------------------
__global__ void gemm_scores(const float* __restrict__ Q,
                            const float* __restrict__ K,
                            float* __restrict__ S) {
    __shared__ float Qs[16][68];  // [k][n]
    __shared__ float Ks[16][68];  // [k][m]

    const int b  = blockIdx.z;
    const int n0 = blockIdx.y * 64;
    const int m0 = blockIdx.x * 64;
    const float* Qb = Q + (size_t)b * CC * NN;
    const float* Kb = K + (size_t)b * CC * NN;
    float* Sb       = S + (size_t)b * NN * NN;

    const int tid = threadIdx.x;
    const int tx  = tid & 15;
    const int ty  = tid >> 4;

    float acc[4][4] = {};

    for (int k0 = 0; k0 < CC; k0 += 16) {
#pragma unroll
        for (int p = 0; p < 4; p++) {
            int idx = tid + p * 256;
            int r = idx >> 6, c = idx & 63;
            Qs[r][c] = Qb[(size_t)(k0 + r) * NN + (n0 + c)];
            Ks[r][c] = Kb[(size_t)(k0 + r) * NN + (m0 + c)];
        }
        __syncthreads();
#pragma unroll
        for (int kk = 0; kk < 16; kk++) {
            float4 a4 = *(const float4*)&Qs[kk][ty * 4];
            float4 b4 = *(const float4*)&Ks[kk][tx * 4];
            float a[4] = {a4.x, a4.y, a4.z, a4.w};
            float bb[4] = {b4.x, b4.y, b4.z, b4.w};
#pragma unroll
            for (int i = 0; i < 4; i++)
#pragma unroll
                for (int j = 0; j < 4; j++) acc[i][j] = fmaf(a[i], bb[j], acc[i][j]);
        }
        __syncthreads();
    }

#pragma unroll
    for (int i = 0; i < 4; i++) {
        size_t row = (size_t)(n0 + ty * 4 + i) * NN;
#pragma unroll
        for (int j = 0; j < 4; j++)
            Sb[row + (m0 + tx * 4 + j)] = acc[i][j];
    }
}

// ---------------------------------------------------------------------------
// Row softmax (in place). One block per row; row held in registers (16/thread).
// ---------------------------------------------------------------------------
__global__ void softmax_rows(float* __restrict__ S) {
    __shared__ float red[256];
    float* p = S + (size_t)blockIdx.x * NN;
    const int tid = threadIdx.x;

    float r[16];
    float mx = -INFINITY;
#pragma unroll
    for (int i = 0; i < 16; i++) {
        r[i] = p[tid + i * 256];
        mx = fmaxf(mx, r[i]);
    }
    red[tid] = mx;
    __syncthreads();
    for (int s = 128; s > 0; s >>= 1) {
        if (tid < s) red[tid] = fmaxf(red[tid], red[tid + s]);
        __syncthreads();
    }
    mx = red[0];
    __syncthreads();

    float sum = 0.0f;
#pragma unroll
    for (int i = 0; i < 16; i++) {
        r[i] = __expf(r[i] - mx);
        sum += r[i];
    }
    red[tid] = sum;
    __syncthreads();
    for (int s = 128; s > 0; s >>= 1) {
        if (tid < s) red[tid] += red[tid + s];
        __syncthreads();
    }
    float inv = 1.0f / red[0];

#pragma unroll
    for (int i = 0; i < 16; i++) p[tid + i * 256] = r[i] * inv;
}

// ---------------------------------------------------------------------------
// AV: out[b][c][n] = sum_m v[b][c][m] * attn[b][n][m]   (NT: K fast in both)
// ---------------------------------------------------------------------------
__global__ void gemm_av(const float* __restrict__ V,
                        const float* __restrict__ A,
                        float* __restrict__ out) {
    __shared__ float Vs[16][68];  // [m][c]
    __shared__ float As[16][68];  // [m][n]

    const int b  = blockIdx.z;
    const int c0 = blockIdx.y * 64;
    const int n0 = blockIdx.x * 64;
    const float* Vb = V + (size_t)b * CC * NN;
    const float* Ab = A + (size_t)b * NN * NN;
    float* Ob       = out + (size_t)b * CC * NN;

    const int tid = threadIdx.x;
    const int tx  = tid & 15;
    const int ty  = tid >> 4;

    float acc[4][4] = {};

    for (int m0 = 0; m0 < NN; m0 += 16) {
#pragma unroll
        for (int p = 0; p < 4; p++) {
            int idx = tid + p * 256;
            int r = idx >> 4, c = idx & 15;  // r: row within 64, c: m within 16
            Vs[c][r] = Vb[(size_t)(c0 + r) * NN + (m0 + c)];
            As[c][r] = Ab[(size_t)(n0 + r) * NN + (m0 + c)];
        }
        __syncthreads();
#pragma unroll
        for (int kk = 0; kk < 16; kk++) {
            float4 a4 = *(const float4*)&Vs[kk][ty * 4];
            float4 b4 = *(const float4*)&As[kk][tx * 4];
            float a[4] = {a4.x, a4.y, a4.z, a4.w};
            float bb[4] = {b4.x, b4.y, b4.z, b4.w};
#pragma unroll
            for (int i = 0; i < 4; i++)
#pragma unroll
                for (int j = 0; j < 4; j++) acc[i][j] = fmaf(a[i], bb[j], acc[i][j]);
        }
        __syncthreads();
    }

#pragma unroll
    for (int i = 0; i < 4; i++) {
        size_t row = (size_t)(c0 + ty * 4 + i) * NN;
#pragma unroll
        for (int j = 0; j < 4; j++)
            Ob[row + (n0 + tx * 4 + j)] = acc[i][j];
    }
}

// ---------------------------------------------------------------------------
// Launch
// ---------------------------------------------------------------------------
extern "C" void kernel_launch(void* const* d_in, const int* in_sizes, int n_in,
                              void* d_out, int out_size) {
    const float* x_q  = (const float*)d_in[0];   // query_input  [B,Cin,H,W]
    const float* x_kv = (const float*)d_in[1];   // key_value_input
    const float* Wq = (const float*)d_in[2];
    const float* bq = (const float*)d_in[3];
    const float* Wk = (const float*)d_in[4];
    const float* bk = (const float*)d_in[5];
    const float* Wv = (const float*)d_in[6];
    const float* bv = (const float*)d_in[7];
    const float* W1 = (const float*)d_in[8];
    const float* b1 = (const float*)d_in[9];
    const float* W2 = (const float*)d_in[10];
    const float* b2 = (const float*)d_in[11];
    float* out = (float*)d_out;

    float *pq, *pk, *pv, *ps, *pav, *ph;
    cudaGetSymbolAddress((void**)&pq, g_q);
    cudaGetSymbolAddress((void**)&pk, g_k);
    cudaGetSymbolAddress((void**)&pv, g_v);
    cudaGetSymbolAddress((void**)&ps, g_s);
    cudaGetSymbolAddress((void**)&pav, g_av);
    cudaGetSymbolAddress((void**)&ph, g_h);

    dim3 tb(256);
    dim3 gProj(NN / 64, CC / 64, BB);    // 64 x 4 x 4
    dim3 gScore(NN / 64, NN / 64, BB);   // 64 x 64 x 4

    gemm_wx<false><<<gProj, tb>>>(Wq, x_q,  bq, pq);
    gemm_wx<false><<<gProj, tb>>>(Wk, x_kv, bk, pk);
    gemm_wx<false><<<gProj, tb>>>(Wv, x_kv, bv, pv);

    gemm_scores<<<gScore, tb>>>(pq, pk, ps);
    softmax_rows<<<BB * NN, tb>>>(ps);
    gemm_av<<<gProj, tb>>>(pv, ps, pav);

    gemm_wx<true ><<<gProj, tb>>>(W1, pav, b1, ph);
    gemm_wx<false><<<gProj, tb>>>(W2, ph,  b2, out);
}

// round 2
// speedup vs baseline: 1.1627x; 1.1627x over previous
#include <cuda_runtime.h>
#include <math.h>
#include <stddef.h>

#define BB 4
#define CC 256
#define NN 4096

// Scratch (allocation-free rule: __device__ globals)
__device__ float g_q[BB * CC * NN];
__device__ float g_k[BB * CC * NN];
__device__ float g_v[BB * CC * NN];
__device__ float g_s[(size_t)BB * NN * NN];   // 256 MB scores/attn
__device__ float g_av[BB * CC * NN];
__device__ float g_h[BB * CC * NN];

// Tile config: 128x128 block tile, BK=16, 256 threads, 8x8 per thread.
#define BK 16
#define PAD 132   // 128 + 4 floats row pitch

// Inner product update: a-frag (8) x b-frag (8) from smem rows
__device__ __forceinline__ void mm_step(const float (*As)[PAD], const float (*Bs)[PAD],
                                        int kk, int ty, int tx, float acc[8][8]) {
    float4 a0 = *(const float4*)&As[kk][ty * 8];
    float4 a1 = *(const float4*)&As[kk][ty * 8 + 4];
    float4 b0 = *(const float4*)&Bs[kk][tx * 8];
    float4 b1 = *(const float4*)&Bs[kk][tx * 8 + 4];
    float a[8] = {a0.x, a0.y, a0.z, a0.w, a1.x, a1.y, a1.z, a1.w};
    float b[8] = {b0.x, b0.y, b0.z, b0.w, b1.x, b1.y, b1.z, b1.w};
#pragma unroll
    for (int i = 0; i < 8; i++)
#pragma unroll
        for (int j = 0; j < 8; j++) acc[i][j] = fmaf(a[i], b[j], acc[i][j]);
}

// ---------------------------------------------------------------------------
// Projection: out[b][o][n] = sum_c W[o][c] * X[b][c][n] + bias[o]
// W row-major [o][c]; X [b][c][n] n-fast. Tile: 128 o x 128 n, K=c.
// ---------------------------------------------------------------------------
template <bool RELU>
__global__ __launch_bounds__(256, 2)
void gemm_wx(const float* __restrict__ W, const float* __restrict__ X,
             const float* __restrict__ bias, float* __restrict__ out) {
    __shared__ float Ws[BK][PAD];   // [k][o]
    __shared__ float Xs[BK][PAD];   // [k][n]

    const int b  = blockIdx.z;
    const int o0 = blockIdx.y * 128;
    const int n0 = blockIdx.x * 128;
    const float* Xb = X + (size_t)b * CC * NN;
    float* Ob       = out + (size_t)b * CC * NN;

    const int tid = threadIdx.x;
    const int tx  = tid & 15;
    const int ty  = tid >> 4;

    // W tile mapping: f = tid*2+p, r = f>>2 (o, 0..127), c4 = f&3 (k/4)
    // X tile mapping: f = tid*2+p, r = f>>5 (k, 0..15), c  = f&31 (n/4)
    float4 wst[2], xst[2];

    auto loadW = [&](int k0) {
#pragma unroll
        for (int p = 0; p < 2; p++) {
            int f = tid * 2 + p;
            wst[p] = *(const float4*)&W[(size_t)(o0 + (f >> 2)) * CC + k0 + (f & 3) * 4];
        }
    };
    auto loadX = [&](int k0) {
#pragma unroll
        for (int p = 0; p < 2; p++) {
            int f = tid * 2 + p;
            xst[p] = *(const float4*)&Xb[(size_t)(k0 + (f >> 5)) * NN + n0 + (f & 31) * 4];
        }
    };
    auto stageToSmem = [&]() {
#pragma unroll
        for (int p = 0; p < 2; p++) {
            int f = tid * 2 + p;
            int r = f >> 2, c4 = f & 3;
            Ws[c4 * 4 + 0][r] = wst[p].x;
            Ws[c4 * 4 + 1][r] = wst[p].y;
            Ws[c4 * 4 + 2][r] = wst[p].z;
            Ws[c4 * 4 + 3][r] = wst[p].w;
            *(float4*)&Xs[f >> 5][(f & 31) * 4] = xst[p];
        }
    };

    float acc[8][8] = {};

    loadW(0); loadX(0);
    stageToSmem();
    __syncthreads();

    for (int k0 = 0; k0 < CC; k0 += BK) {
        bool more = (k0 + BK) < CC;
        if (more) { loadW(k0 + BK); loadX(k0 + BK); }
#pragma unroll
        for (int kk = 0; kk < BK; kk++) mm_step(Ws, Xs, kk, ty, tx, acc);
        if (more) {
            __syncthreads();
            stageToSmem();
            __syncthreads();
        }
    }

#pragma unroll
    for (int i = 0; i < 8; i++) {
        int o = o0 + ty * 8 + i;
        float bs = bias[o];
        float4 v0, v1;
        v0.x = acc[i][0] + bs; v0.y = acc[i][1] + bs; v0.z = acc[i][2] + bs; v0.w = acc[i][3] + bs;
        v1.x = acc[i][4] + bs; v1.y = acc[i][5] + bs; v1.z = acc[i][6] + bs; v1.w = acc[i][7] + bs;
        if (RELU) {
            v0.x = fmaxf(v0.x, 0.f); v0.y = fmaxf(v0.y, 0.f); v0.z = fmaxf(v0.z, 0.f); v0.w = fmaxf(v0.w, 0.f);
            v1.x = fmaxf(v1.x, 0.f); v1.y = fmaxf(v1.y, 0.f); v1.z = fmaxf(v1.z, 0.f); v1.w = fmaxf(v1.w, 0.f);
        }
        *(float4*)&Ob[(size_t)o * NN + n0 + tx * 8]     = v0;
        *(float4*)&Ob[(size_t)o * NN + n0 + tx * 8 + 4] = v1;
    }
}

// ---------------------------------------------------------------------------
// Scores: S[b][n][m] = sum_c Q[b][c][n] * K[b][c][m]  (both n/m-fast, k slow)
// ---------------------------------------------------------------------------
__global__ __launch_bounds__(256, 2)
void gemm_scores(const float* __restrict__ Q, const float* __restrict__ K,
                 float* __restrict__ S) {
    __shared__ float Qs[BK][PAD];   // [k][n]
    __shared__ float Ks[BK][PAD];   // [k][m]

    const int b  = blockIdx.z;
    const int n0 = blockIdx.y * 128;
    const int m0 = blockIdx.x * 128;
    const float* Qb = Q + (size_t)b * CC * NN;
    const float* Kb = K + (size_t)b * CC * NN;
    float* Sb       = S + (size_t)b * NN * NN;

    const int tid = threadIdx.x;
    const int tx  = tid & 15;
    const int ty  = tid >> 4;

    float4 qst[2], kst[2];

    auto loadTiles = [&](int k0) {
#pragma unroll
        for (int p = 0; p < 2; p++) {
            int f = tid * 2 + p;
            size_t off = (size_t)(k0 + (f >> 5)) * NN + (f & 31) * 4;
            qst[p] = *(const float4*)&Qb[off + n0];
            kst[p] = *(const float4*)&Kb[off + m0];
        }
    };
    auto stageToSmem = [&]() {
#pragma unroll
        for (int p = 0; p < 2; p++) {
            int f = tid * 2 + p;
            *(float4*)&Qs[f >> 5][(f & 31) * 4] = qst[p];
            *(float4*)&Ks[f >> 5][(f & 31) * 4] = kst[p];
        }
    };

    float acc[8][8] = {};

    loadTiles(0);
    stageToSmem();
    __syncthreads();

    for (int k0 = 0; k0 < CC; k0 += BK) {
        bool more = (k0 + BK) < CC;
        if (more) loadTiles(k0 + BK);
#pragma unroll
        for (int kk = 0; kk < BK; kk++) mm_step(Qs, Ks, kk, ty, tx, acc);
        if (more) {
            __syncthreads();
            stageToSmem();
            __syncthreads();
        }
    }

#pragma unroll
    for (int i = 0; i < 8; i++) {
        size_t row = (size_t)(n0 + ty * 8 + i) * NN + m0 + tx * 8;
        *(float4*)&Sb[row]     = make_float4(acc[i][0], acc[i][1], acc[i][2], acc[i][3]);
        *(float4*)&Sb[row + 4] = make_float4(acc[i][4], acc[i][5], acc[i][6], acc[i][7]);
    }
}

// ---------------------------------------------------------------------------
// AV: out[b][c][n] = sum_m V[b][c][m] * A[b][n][m]   (m fast in both)
// ---------------------------------------------------------------------------
__global__ __launch_bounds__(256, 2)
void gemm_av(const float* __restrict__ V, const float* __restrict__ A,
             float* __restrict__ out) {
    __shared__ float Vs[BK][PAD];   // [m][c]
    __shared__ float As[BK][PAD];   // [m][n]

    const int b  = blockIdx.z;
    const int c0 = blockIdx.y * 128;
    const int n0 = blockIdx.x * 128;
    const float* Vb = V + (size_t)b * CC * NN;
    const float* Ab = A + (size_t)b * NN * NN;
    float* Ob       = out + (size_t)b * CC * NN;

    const int tid = threadIdx.x;
    const int tx  = tid & 15;
    const int ty  = tid >> 4;

    // Both tiles: f = tid*2+p; r = f>>2 (row 0..127), c4 = f&3 (m/4)
    float4 vst[2], ast[2];

    auto loadTiles = [&](int m0t) {
#pragma unroll
        for (int p = 0; p < 2; p++) {
            int f = tid * 2 + p;
            int r = f >> 2, c4 = f & 3;
            vst[p] = *(const float4*)&Vb[(size_t)(c0 + r) * NN + m0t + c4 * 4];
            ast[p] = *(const float4*)&Ab[(size_t)(n0 + r) * NN + m0t + c4 * 4];
        }
    };
    auto stageToSmem = [&]() {
#pragma unroll
        for (int p = 0; p < 2; p++) {
            int f = tid * 2 + p;
            int r = f >> 2, c4 = f & 3;
            Vs[c4 * 4 + 0][r] = vst[p].x;
            Vs[c4 * 4 + 1][r] = vst[p].y;
            Vs[c4 * 4 + 2][r] = vst[p].z;
            Vs[c4 * 4 + 3][r] = vst[p].w;
            As[c4 * 4 + 0][r] = ast[p].x;
            As[c4 * 4 + 1][r] = ast[p].y;
            As[c4 * 4 + 2][r] = ast[p].z;
            As[c4 * 4 + 3][r] = ast[p].w;
        }
    };

    float acc[8][8] = {};

    loadTiles(0);
    stageToSmem();
    __syncthreads();

    for (int m0t = 0; m0t < NN; m0t += BK) {
        bool more = (m0t + BK) < NN;
        if (more) loadTiles(m0t + BK);
#pragma unroll
        for (int kk = 0; kk < BK; kk++) mm_step(Vs, As, kk, ty, tx, acc);
        if (more) {
            __syncthreads();
            stageToSmem();
            __syncthreads();
        }
    }

#pragma unroll
    for (int i = 0; i < 8; i++) {
        size_t row = (size_t)(c0 + ty * 8 + i) * NN + n0 + tx * 8;
        *(float4*)&Ob[row]     = make_float4(acc[i][0], acc[i][1], acc[i][2], acc[i][3]);
        *(float4*)&Ob[row + 4] = make_float4(acc[i][4], acc[i][5], acc[i][6], acc[i][7]);
    }
}

// ---------------------------------------------------------------------------
// Row softmax (in place). One block (256 thr) per row, float4, reg-resident.
// ---------------------------------------------------------------------------
__global__ void softmax_rows(float* __restrict__ S) {
    __shared__ float red[256];
    float4* p = (float4*)(S + (size_t)blockIdx.x * NN);
    const int tid = threadIdx.x;

    float4 r[4];
    float mx = -INFINITY;
#pragma unroll
    for (int i = 0; i < 4; i++) {
        r[i] = p[tid + i * 256];
        mx = fmaxf(mx, fmaxf(fmaxf(r[i].x, r[i].y), fmaxf(r[i].z, r[i].w)));
    }
    red[tid] = mx;
    __syncthreads();
    for (int s = 128; s > 0; s >>= 1) {
        if (tid < s) red[tid] = fmaxf(red[tid], red[tid + s]);
        __syncthreads();
    }
    mx = red[0];
    __syncthreads();

    float sum = 0.0f;
#pragma unroll
    for (int i = 0; i < 4; i++) {
        r[i].x = __expf(r[i].x - mx); r[i].y = __expf(r[i].y - mx);
        r[i].z = __expf(r[i].z - mx); r[i].w = __expf(r[i].w - mx);
        sum += r[i].x + r[i].y + r[i].z + r[i].w;
    }
    red[tid] = sum;
    __syncthreads();
    for (int s = 128; s > 0; s >>= 1) {
        if (tid < s) red[tid] += red[tid + s];
        __syncthreads();
    }
    float inv = 1.0f / red[0];

#pragma unroll
    for (int i = 0; i < 4; i++) {
        r[i].x *= inv; r[i].y *= inv; r[i].z *= inv; r[i].w *= inv;
        p[tid + i * 256] = r[i];
    }
}

// ---------------------------------------------------------------------------
extern "C" void kernel_launch(void* const* d_in, const int* in_sizes, int n_in,
                              void* d_out, int out_size) {
    const float* x_q  = (const float*)d_in[0];
    const float* x_kv = (const float*)d_in[1];
    const float* Wq = (const float*)d_in[2];
    const float* bq = (const float*)d_in[3];
    const float* Wk = (const float*)d_in[4];
    const float* bk = (const float*)d_in[5];
    const float* Wv = (const float*)d_in[6];
    const float* bv = (const float*)d_in[7];
    const float* W1 = (const float*)d_in[8];
    const float* b1 = (const float*)d_in[9];
    const float* W2 = (const float*)d_in[10];
    const float* b2 = (const float*)d_in[11];
    float* out = (float*)d_out;

    float *pq, *pk, *pv, *ps, *pav, *ph;
    cudaGetSymbolAddress((void**)&pq, g_q);
    cudaGetSymbolAddress((void**)&pk, g_k);
    cudaGetSymbolAddress((void**)&pv, g_v);
    cudaGetSymbolAddress((void**)&ps, g_s);
    cudaGetSymbolAddress((void**)&pav, g_av);
    cudaGetSymbolAddress((void**)&ph, g_h);

    dim3 tb(256);
    dim3 gProj(NN / 128, CC / 128, BB);    // 32 x 2 x 4
    dim3 gScore(NN / 128, NN / 128, BB);   // 32 x 32 x 4

    gemm_wx<false><<<gProj, tb>>>(Wq, x_q,  bq, pq);
    gemm_wx<false><<<gProj, tb>>>(Wk, x_kv, bk, pk);
    gemm_wx<false><<<gProj, tb>>>(Wv, x_kv, bv, pv);

    gemm_scores<<<gScore, tb>>>(pq, pk, ps);
    softmax_rows<<<BB * NN, tb>>>(ps);
    gemm_av<<<gProj, tb>>>(pv, ps, pav);

    gemm_wx<true ><<<gProj, tb>>>(W1, pav, b1, ph);
    gemm_wx<false><<<gProj, tb>>>(W2, ph,  b2, out);
}

// round 3
// speedup vs baseline: 1.3125x; 1.1288x over previous
#include <cuda_runtime.h>
#include <math.h>
#include <stddef.h>

#define BB 4
#define CC 256
#define NN 4096

// Scratch (allocation-free rule: __device__ globals)
__device__ float g_q[BB * CC * NN];
__device__ float g_k[BB * CC * NN];
__device__ float g_v[BB * CC * NN];
__device__ float g_s[(size_t)BB * NN * NN];   // 256 MB scores/attn
__device__ float g_av[BB * CC * NN];
__device__ float g_h[BB * CC * NN];

// Tile config: 128x128 block tile, BK=16, 256 threads.
// Microtile: 2x2 blocks of 4x4 per thread, block stride 64 (bank-conflict-free).
#define BK 16
#define PAD 132   // row pitch in floats

// acc[i][j]: i = h*4+r -> row h*64 + ty*4 + r ; j = g*4+c -> col g*64 + tx*4 + c
__device__ __forceinline__ void mm_step(const float (*As)[PAD], const float (*Bs)[PAD],
                                        int kk, int ty, int tx, float acc[8][8]) {
    float4 a0 = *(const float4*)&As[kk][ty * 4];
    float4 a1 = *(const float4*)&As[kk][64 + ty * 4];
    float4 b0 = *(const float4*)&Bs[kk][tx * 4];
    float4 b1 = *(const float4*)&Bs[kk][64 + tx * 4];
    float a[8] = {a0.x, a0.y, a0.z, a0.w, a1.x, a1.y, a1.z, a1.w};
    float b[8] = {b0.x, b0.y, b0.z, b0.w, b1.x, b1.y, b1.z, b1.w};
#pragma unroll
    for (int i = 0; i < 8; i++)
#pragma unroll
        for (int j = 0; j < 8; j++) acc[i][j] = fmaf(a[i], b[j], acc[i][j]);
}

// ---------------------------------------------------------------------------
// Projection: out[b][o][n] = sum_c W[o][c] * X[b][c][n] + bias[o]
// ---------------------------------------------------------------------------
template <bool RELU>
__global__ __launch_bounds__(256, 2)
void gemm_wx(const float* __restrict__ W, const float* __restrict__ X,
             const float* __restrict__ bias, float* __restrict__ out) {
    __shared__ float Ws[2][BK][PAD];   // [k][o]
    __shared__ float Xs[2][BK][PAD];   // [k][n]

    const int b  = blockIdx.z;
    const int o0 = blockIdx.y * 128;
    const int n0 = blockIdx.x * 128;
    const float* Xb = X + (size_t)b * CC * NN;
    float* Ob       = out + (size_t)b * CC * NN;

    const int tid = threadIdx.x;
    const int tx  = tid & 15;
    const int ty  = tid >> 4;

    float4 wst[2], xst[2];

    auto loadTiles = [&](int k0) {
#pragma unroll
        for (int p = 0; p < 2; p++) {
            int f = tid * 2 + p;
            // W: r = f>>2 (o row), c4 = f&3 (k/4)
            wst[p] = *(const float4*)&W[(size_t)(o0 + (f >> 2)) * CC + k0 + (f & 3) * 4];
            // X: r = f>>5 (k row), c = f&31 (n/4)
            xst[p] = *(const float4*)&Xb[(size_t)(k0 + (f >> 5)) * NN + n0 + (f & 31) * 4];
        }
    };
    auto stage = [&](int s) {
#pragma unroll
        for (int p = 0; p < 2; p++) {
            int f = tid * 2 + p;
            int r = f >> 2, c4 = f & 3;
            Ws[s][c4 * 4 + 0][r] = wst[p].x;
            Ws[s][c4 * 4 + 1][r] = wst[p].y;
            Ws[s][c4 * 4 + 2][r] = wst[p].z;
            Ws[s][c4 * 4 + 3][r] = wst[p].w;
            *(float4*)&Xs[s][f >> 5][(f & 31) * 4] = xst[p];
        }
    };

    float acc[8][8] = {};

    loadTiles(0);
    stage(0);
    __syncthreads();

    const int NSTEP = CC / BK;
    for (int s = 0; s < NSTEP; s++) {
        int buf = s & 1;
        bool more = (s + 1) < NSTEP;
        if (more) loadTiles((s + 1) * BK);
#pragma unroll
        for (int kk = 0; kk < BK; kk++) mm_step(Ws[buf], Xs[buf], kk, ty, tx, acc);
        if (more) {
            stage(buf ^ 1);
            __syncthreads();
        }
    }

#pragma unroll
    for (int h = 0; h < 2; h++)
#pragma unroll
    for (int r = 0; r < 4; r++) {
        int i = h * 4 + r;
        int o = o0 + h * 64 + ty * 4 + r;
        float bs = bias[o];
        float4 v0 = make_float4(acc[i][0] + bs, acc[i][1] + bs, acc[i][2] + bs, acc[i][3] + bs);
        float4 v1 = make_float4(acc[i][4] + bs, acc[i][5] + bs, acc[i][6] + bs, acc[i][7] + bs);
        if (RELU) {
            v0.x = fmaxf(v0.x, 0.f); v0.y = fmaxf(v0.y, 0.f); v0.z = fmaxf(v0.z, 0.f); v0.w = fmaxf(v0.w, 0.f);
            v1.x = fmaxf(v1.x, 0.f); v1.y = fmaxf(v1.y, 0.f); v1.z = fmaxf(v1.z, 0.f); v1.w = fmaxf(v1.w, 0.f);
        }
        *(float4*)&Ob[(size_t)o * NN + n0 + tx * 4]      = v0;
        *(float4*)&Ob[(size_t)o * NN + n0 + 64 + tx * 4] = v1;
    }
}

// ---------------------------------------------------------------------------
// Scores: S[b][n][m] = sum_c Q[b][c][n] * K[b][c][m]
// ---------------------------------------------------------------------------
__global__ __launch_bounds__(256, 2)
void gemm_scores(const float* __restrict__ Q, const float* __restrict__ K,
                 float* __restrict__ S) {
    __shared__ float Qs[2][BK][PAD];   // [k][n]
    __shared__ float Ks[2][BK][PAD];   // [k][m]

    const int b  = blockIdx.z;
    const int n0 = blockIdx.y * 128;
    const int m0 = blockIdx.x * 128;
    const float* Qb = Q + (size_t)b * CC * NN;
    const float* Kb = K + (size_t)b * CC * NN;
    float* Sb       = S + (size_t)b * NN * NN;

    const int tid = threadIdx.x;
    const int tx  = tid & 15;
    const int ty  = tid >> 4;

    float4 qst[2], kst[2];

    auto loadTiles = [&](int k0) {
#pragma unroll
        for (int p = 0; p < 2; p++) {
            int f = tid * 2 + p;
            size_t off = (size_t)(k0 + (f >> 5)) * NN + (f & 31) * 4;
            qst[p] = *(const float4*)&Qb[off + n0];
            kst[p] = *(const float4*)&Kb[off + m0];
        }
    };
    auto stage = [&](int s) {
#pragma unroll
        for (int p = 0; p < 2; p++) {
            int f = tid * 2 + p;
            *(float4*)&Qs[s][f >> 5][(f & 31) * 4] = qst[p];
            *(float4*)&Ks[s][f >> 5][(f & 31) * 4] = kst[p];
        }
    };

    float acc[8][8] = {};

    loadTiles(0);
    stage(0);
    __syncthreads();

    const int NSTEP = CC / BK;
    for (int s = 0; s < NSTEP; s++) {
        int buf = s & 1;
        bool more = (s + 1) < NSTEP;
        if (more) loadTiles((s + 1) * BK);
#pragma unroll
        for (int kk = 0; kk < BK; kk++) mm_step(Qs[buf], Ks[buf], kk, ty, tx, acc);
        if (more) {
            stage(buf ^ 1);
            __syncthreads();
        }
    }

#pragma unroll
    for (int h = 0; h < 2; h++)
#pragma unroll
    for (int r = 0; r < 4; r++) {
        int i = h * 4 + r;
        size_t row = (size_t)(n0 + h * 64 + ty * 4 + r) * NN;
        *(float4*)&Sb[row + m0 + tx * 4]      = make_float4(acc[i][0], acc[i][1], acc[i][2], acc[i][3]);
        *(float4*)&Sb[row + m0 + 64 + tx * 4] = make_float4(acc[i][4], acc[i][5], acc[i][6], acc[i][7]);
    }
}

// ---------------------------------------------------------------------------
// AV: out[b][c][n] = sum_m V[b][c][m] * A[b][n][m]
// ---------------------------------------------------------------------------
__global__ __launch_bounds__(256, 2)
void gemm_av(const float* __restrict__ V, const float* __restrict__ A,
             float* __restrict__ out) {
    __shared__ float Vs[2][BK][PAD];   // [m][c]
    __shared__ float As[2][BK][PAD];   // [m][n]

    const int b  = blockIdx.z;
    const int c0 = blockIdx.y * 128;
    const int n0 = blockIdx.x * 128;
    const float* Vb = V + (size_t)b * CC * NN;
    const float* Ab = A + (size_t)b * NN * NN;
    float* Ob       = out + (size_t)b * CC * NN;

    const int tid = threadIdx.x;
    const int tx  = tid & 15;
    const int ty  = tid >> 4;

    float4 vst[2], ast[2];

    auto loadTiles = [&](int m0t) {
#pragma unroll
        for (int p = 0; p < 2; p++) {
            int f = tid * 2 + p;
            int r = f >> 2, c4 = f & 3;
            vst[p] = *(const float4*)&Vb[(size_t)(c0 + r) * NN + m0t + c4 * 4];
            ast[p] = *(const float4*)&Ab[(size_t)(n0 + r) * NN + m0t + c4 * 4];
        }
    };
    auto stage = [&](int s) {
#pragma unroll
        for (int p = 0; p < 2; p++) {
            int f = tid * 2 + p;
            int r = f >> 2, c4 = f & 3;
            Vs[s][c4 * 4 + 0][r] = vst[p].x;
            Vs[s][c4 * 4 + 1][r] = vst[p].y;
            Vs[s][c4 * 4 + 2][r] = vst[p].z;
            Vs[s][c4 * 4 + 3][r] = vst[p].w;
            As[s][c4 * 4 + 0][r] = ast[p].x;
            As[s][c4 * 4 + 1][r] = ast[p].y;
            As[s][c4 * 4 + 2][r] = ast[p].z;
            As[s][c4 * 4 + 3][r] = ast[p].w;
        }
    };

    float acc[8][8] = {};

    loadTiles(0);
    stage(0);
    __syncthreads();

    const int NSTEP = NN / BK;
    for (int s = 0; s < NSTEP; s++) {
        int buf = s & 1;
        bool more = (s + 1) < NSTEP;
        if (more) loadTiles((s + 1) * BK);
#pragma unroll
        for (int kk = 0; kk < BK; kk++) mm_step(Vs[buf], As[buf], kk, ty, tx, acc);
        if (more) {
            stage(buf ^ 1);
            __syncthreads();
        }
    }

#pragma unroll
    for (int h = 0; h < 2; h++)
#pragma unroll
    for (int r = 0; r < 4; r++) {
        int i = h * 4 + r;
        size_t row = (size_t)(c0 + h * 64 + ty * 4 + r) * NN;
        *(float4*)&Ob[row + n0 + tx * 4]      = make_float4(acc[i][0], acc[i][1], acc[i][2], acc[i][3]);
        *(float4*)&Ob[row + n0 + 64 + tx * 4] = make_float4(acc[i][4], acc[i][5], acc[i][6], acc[i][7]);
    }
}

// ---------------------------------------------------------------------------
// Row softmax (in place).
// ---------------------------------------------------------------------------
__global__ void softmax_rows(float* __restrict__ S) {
    __shared__ float red[256];
    float4* p = (float4*)(S + (size_t)blockIdx.x * NN);
    const int tid = threadIdx.x;

    float4 r[4];
    float mx = -INFINITY;
#pragma unroll
    for (int i = 0; i < 4; i++) {
        r[i] = p[tid + i * 256];
        mx = fmaxf(mx, fmaxf(fmaxf(r[i].x, r[i].y), fmaxf(r[i].z, r[i].w)));
    }
    red[tid] = mx;
    __syncthreads();
    for (int s = 128; s > 0; s >>= 1) {
        if (tid < s) red[tid] = fmaxf(red[tid], red[tid + s]);
        __syncthreads();
    }
    mx = red[0];
    __syncthreads();

    float sum = 0.0f;
#pragma unroll
    for (int i = 0; i < 4; i++) {
        r[i].x = __expf(r[i].x - mx); r[i].y = __expf(r[i].y - mx);
        r[i].z = __expf(r[i].z - mx); r[i].w = __expf(r[i].w - mx);
        sum += r[i].x + r[i].y + r[i].z + r[i].w;
    }
    red[tid] = sum;
    __syncthreads();
    for (int s = 128; s > 0; s >>= 1) {
        if (tid < s) red[tid] += red[tid + s];
        __syncthreads();
    }
    float inv = 1.0f / red[0];

#pragma unroll
    for (int i = 0; i < 4; i++) {
        r[i].x *= inv; r[i].y *= inv; r[i].z *= inv; r[i].w *= inv;
        p[tid + i * 256] = r[i];
    }
}

// ---------------------------------------------------------------------------
extern "C" void kernel_launch(void* const* d_in, const int* in_sizes, int n_in,
                              void* d_out, int out_size) {
    const float* x_q  = (const float*)d_in[0];
    const float* x_kv = (const float*)d_in[1];
    const float* Wq = (const float*)d_in[2];
    const float* bq = (const float*)d_in[3];
    const float* Wk = (const float*)d_in[4];
    const float* bk = (const float*)d_in[5];
    const float* Wv = (const float*)d_in[6];
    const float* bv = (const float*)d_in[7];
    const float* W1 = (const float*)d_in[8];
    const float* b1 = (const float*)d_in[9];
    const float* W2 = (const float*)d_in[10];
    const float* b2 = (const float*)d_in[11];
    float* out = (float*)d_out;

    float *pq, *pk, *pv, *ps, *pav, *ph;
    cudaGetSymbolAddress((void**)&pq, g_q);
    cudaGetSymbolAddress((void**)&pk, g_k);
    cudaGetSymbolAddress((void**)&pv, g_v);
    cudaGetSymbolAddress((void**)&ps, g_s);
    cudaGetSymbolAddress((void**)&pav, g_av);
    cudaGetSymbolAddress((void**)&ph, g_h);

    dim3 tb(256);
    dim3 gProj(NN / 128, CC / 128, BB);    // 32 x 2 x 4
    dim3 gScore(NN / 128, NN / 128, BB);   // 32 x 32 x 4

    gemm_wx<false><<<gProj, tb>>>(Wq, x_q,  bq, pq);
    gemm_wx<false><<<gProj, tb>>>(Wk, x_kv, bk, pk);
    gemm_wx<false><<<gProj, tb>>>(Wv, x_kv, bv, pv);

    gemm_scores<<<gScore, tb>>>(pq, pk, ps);
    softmax_rows<<<BB * NN, tb>>>(ps);
    gemm_av<<<gProj, tb>>>(pv, ps, pav);

    gemm_wx<true ><<<gProj, tb>>>(W1, pav, b1, ph);
    gemm_wx<false><<<gProj, tb>>>(W2, ph,  b2, out);
}

// round 4
// speedup vs baseline: 1.9275x; 1.4686x over previous
#include <cuda_runtime.h>
#include <cuda_bf16.h>
#include <math.h>
#include <stddef.h>
#include <stdint.h>

#define BB 4
#define CC 256
#define NN 4096

// Scratch (__device__ globals; no allocation allowed)
__device__ __nv_bfloat16 g_qh[(size_t)BB * NN * CC];   // [b][n][c]
__device__ __nv_bfloat16 g_ql[(size_t)BB * NN * CC];
__device__ __nv_bfloat16 g_kh[(size_t)BB * NN * CC];   // [b][m][c]
__device__ __nv_bfloat16 g_kl[(size_t)BB * NN * CC];
__device__ __nv_bfloat16 g_vh[(size_t)BB * CC * NN];   // [b][c][m]
__device__ __nv_bfloat16 g_vl[(size_t)BB * CC * NN];
__device__ float         g_s [(size_t)BB * NN * NN];   // scores fp32 (256MB)
__device__ __nv_bfloat16 g_ah[(size_t)BB * NN * NN];   // attn hi [b][n][m]
__device__ __nv_bfloat16 g_al[(size_t)BB * NN * NN];   // attn lo
__device__ float         g_av[(size_t)BB * CC * NN];
__device__ float         g_hid[(size_t)BB * CC * NN];

// ---------------------------------------------------------------------------
// helpers
// ---------------------------------------------------------------------------
__device__ __forceinline__ void split_bf16(float f, unsigned short& h, unsigned short& l) {
    __nv_bfloat16 hb = __float2bfloat16(f);
    float r = f - __bfloat162float(hb);
    __nv_bfloat16 lb = __float2bfloat16(r);
    h = __bfloat16_as_ushort(hb);
    l = __bfloat16_as_ushort(lb);
}

__device__ __forceinline__ void mma16816(float c[4],
                                         uint32_t a0, uint32_t a1, uint32_t a2, uint32_t a3,
                                         uint32_t b0, uint32_t b1) {
    asm volatile(
        "mma.sync.aligned.m16n8k16.row.col.f32.bf16.bf16.f32 "
        "{%0,%1,%2,%3}, {%4,%5,%6,%7}, {%8,%9}, {%0,%1,%2,%3};"
        : "+f"(c[0]), "+f"(c[1]), "+f"(c[2]), "+f"(c[3])
        : "r"(a0), "r"(a1), "r"(a2), "r"(a3), "r"(b0), "r"(b1));
}

// ---------------------------------------------------------------------------
// Projection GEMM (fp32 mainloop, from R3) with selectable epilogue:
// MODE 0: fp32 out [b][o][n] (+bias, optional relu)
// MODE 1: split bf16 natural  [b][o][n] (V)
// MODE 2: split bf16 transposed [b][n][o] (Q, K)
// ---------------------------------------------------------------------------
#define BK 16
#define PAD 132

__device__ __forceinline__ void mm_step_f32(const float (*As)[PAD], const float (*Bs)[PAD],
                                            int kk, int ty, int tx, float acc[8][8]) {
    float4 a0 = *(const float4*)&As[kk][ty * 4];
    float4 a1 = *(const float4*)&As[kk][64 + ty * 4];
    float4 b0 = *(const float4*)&Bs[kk][tx * 4];
    float4 b1 = *(const float4*)&Bs[kk][64 + tx * 4];
    float a[8] = {a0.x, a0.y, a0.z, a0.w, a1.x, a1.y, a1.z, a1.w};
    float b[8] = {b0.x, b0.y, b0.z, b0.w, b1.x, b1.y, b1.z, b1.w};
#pragma unroll
    for (int i = 0; i < 8; i++)
#pragma unroll
        for (int j = 0; j < 8; j++) acc[i][j] = fmaf(a[i], b[j], acc[i][j]);
}

template <int MODE, bool RELU>
__global__ __launch_bounds__(256, 2)
void gemm_wx(const float* __restrict__ W, const float* __restrict__ X,
             const float* __restrict__ bias,
             float* __restrict__ outF,
             __nv_bfloat16* __restrict__ outH, __nv_bfloat16* __restrict__ outL) {
    __shared__ float Ws[2][BK][PAD];
    __shared__ float Xs[2][BK][PAD];

    const int b  = blockIdx.z;
    const int o0 = blockIdx.y * 128;
    const int n0 = blockIdx.x * 128;
    const float* Xb = X + (size_t)b * CC * NN;

    const int tid = threadIdx.x;
    const int tx  = tid & 15;
    const int ty  = tid >> 4;

    float4 wst[2], xst[2];

    auto loadTiles = [&](int k0) {
#pragma unroll
        for (int p = 0; p < 2; p++) {
            int f = tid * 2 + p;
            wst[p] = *(const float4*)&W[(size_t)(o0 + (f >> 2)) * CC + k0 + (f & 3) * 4];
            xst[p] = *(const float4*)&Xb[(size_t)(k0 + (f >> 5)) * NN + n0 + (f & 31) * 4];
        }
    };
    auto stage = [&](int s) {
#pragma unroll
        for (int p = 0; p < 2; p++) {
            int f = tid * 2 + p;
            int r = f >> 2, c4 = f & 3;
            Ws[s][c4 * 4 + 0][r] = wst[p].x;
            Ws[s][c4 * 4 + 1][r] = wst[p].y;
            Ws[s][c4 * 4 + 2][r] = wst[p].z;
            Ws[s][c4 * 4 + 3][r] = wst[p].w;
            *(float4*)&Xs[s][f >> 5][(f & 31) * 4] = xst[p];
        }
    };

    float acc[8][8] = {};

    loadTiles(0);
    stage(0);
    __syncthreads();

    const int NSTEP = CC / BK;
    for (int s = 0; s < NSTEP; s++) {
        int buf = s & 1;
        bool more = (s + 1) < NSTEP;
        if (more) loadTiles((s + 1) * BK);
#pragma unroll
        for (int kk = 0; kk < BK; kk++) mm_step_f32(Ws[buf], Xs[buf], kk, ty, tx, acc);
        if (more) {
            stage(buf ^ 1);
            __syncthreads();
        }
    }

    if (MODE == 0) {
        float* Ob = outF + (size_t)b * CC * NN;
#pragma unroll
        for (int h = 0; h < 2; h++)
#pragma unroll
        for (int r = 0; r < 4; r++) {
            int i = h * 4 + r;
            int o = o0 + h * 64 + ty * 4 + r;
            float bs = bias[o];
            float4 v0 = make_float4(acc[i][0] + bs, acc[i][1] + bs, acc[i][2] + bs, acc[i][3] + bs);
            float4 v1 = make_float4(acc[i][4] + bs, acc[i][5] + bs, acc[i][6] + bs, acc[i][7] + bs);
            if (RELU) {
                v0.x = fmaxf(v0.x, 0.f); v0.y = fmaxf(v0.y, 0.f); v0.z = fmaxf(v0.z, 0.f); v0.w = fmaxf(v0.w, 0.f);
                v1.x = fmaxf(v1.x, 0.f); v1.y = fmaxf(v1.y, 0.f); v1.z = fmaxf(v1.z, 0.f); v1.w = fmaxf(v1.w, 0.f);
            }
            *(float4*)&Ob[(size_t)o * NN + n0 + tx * 4]      = v0;
            *(float4*)&Ob[(size_t)o * NN + n0 + 64 + tx * 4] = v1;
        }
    } else if (MODE == 1) {
        // natural split [b][o][n]
        __nv_bfloat16* Oh = outH + (size_t)b * CC * NN;
        __nv_bfloat16* Ol = outL + (size_t)b * CC * NN;
#pragma unroll
        for (int h = 0; h < 2; h++)
#pragma unroll
        for (int r = 0; r < 4; r++) {
            int i = h * 4 + r;
            int o = o0 + h * 64 + ty * 4 + r;
            float bs = bias[o];
#pragma unroll
            for (int gblk = 0; gblk < 2; gblk++) {
                unsigned short hs[4], ls[4];
#pragma unroll
                for (int cc = 0; cc < 4; cc++)
                    split_bf16(acc[i][gblk * 4 + cc] + bs, hs[cc], ls[cc]);
                uint2 uh = make_uint2((uint32_t)hs[0] | ((uint32_t)hs[1] << 16),
                                      (uint32_t)hs[2] | ((uint32_t)hs[3] << 16));
                uint2 ul = make_uint2((uint32_t)ls[0] | ((uint32_t)ls[1] << 16),
                                      (uint32_t)ls[2] | ((uint32_t)ls[3] << 16));
                size_t off = (size_t)o * NN + n0 + gblk * 64 + tx * 4;
                *(uint2*)&Oh[off] = uh;
                *(uint2*)&Ol[off] = ul;
            }
        }
    } else {
        // transposed split [b][n][o]
        __nv_bfloat16* Oh = outH + (size_t)b * NN * CC;
        __nv_bfloat16* Ol = outL + (size_t)b * NN * CC;
#pragma unroll
        for (int gblk = 0; gblk < 2; gblk++)
#pragma unroll
        for (int cc = 0; cc < 4; cc++) {
            int j = gblk * 4 + cc;
            int n = n0 + gblk * 64 + tx * 4 + cc;
#pragma unroll
            for (int h = 0; h < 2; h++) {
                int cbase = o0 + h * 64 + ty * 4;
                unsigned short hs[4], ls[4];
#pragma unroll
                for (int r = 0; r < 4; r++)
                    split_bf16(acc[h * 4 + r][j] + bias[cbase + r], hs[r], ls[r]);
                uint2 uh = make_uint2((uint32_t)hs[0] | ((uint32_t)hs[1] << 16),
                                      (uint32_t)hs[2] | ((uint32_t)hs[3] << 16));
                uint2 ul = make_uint2((uint32_t)ls[0] | ((uint32_t)ls[1] << 16),
                                      (uint32_t)ls[2] | ((uint32_t)ls[3] << 16));
                size_t off = (size_t)n * CC + cbase;
                *(uint2*)&Oh[off] = uh;
                *(uint2*)&Ol[off] = ul;
            }
        }
    }
}

// ---------------------------------------------------------------------------
// Tensor-core GEMM: C[row][col] = sum_k (Ah+Al)[row][k] * (Bh+Bl)[col][k]
// 3-term split accumulation. Block 128x128, BKC=32, 256 thr, warp tile 64x32.
// ---------------------------------------------------------------------------
#define BKC 32
#define SPITCH 40   // 32 + 8 bf16 pad -> 80B pitch, conflict-free frag loads

__global__ __launch_bounds__(256)
void mma_gemm(const __nv_bfloat16* __restrict__ Ah, const __nv_bfloat16* __restrict__ Al,
              size_t sAb, int lda,
              const __nv_bfloat16* __restrict__ Bh, const __nv_bfloat16* __restrict__ Bl,
              size_t sBb, int ldb,
              float* __restrict__ C, size_t sCb, int ldc, int Ktot) {
    __shared__ __align__(16) __nv_bfloat16 sA[2][128][SPITCH];
    __shared__ __align__(16) __nv_bfloat16 sB[2][128][SPITCH];

    const int b    = blockIdx.z;
    const int row0 = blockIdx.y * 128;
    const int col0 = blockIdx.x * 128;
    Ah += (size_t)b * sAb;  Al += (size_t)b * sAb;
    Bh += (size_t)b * sBb;  Bl += (size_t)b * sBb;
    C  += (size_t)b * sCb;

    const int tid  = threadIdx.x;
    const int w    = tid >> 5, lane = tid & 31;
    const int g    = lane >> 2, tig = lane & 3;
    const int wm   = (w & 1) * 64;   // warp row offset
    const int wn   = (w >> 1) * 32;  // warp col offset

    uint4 rAh[2], rAl[2], rBh[2], rBl[2];

    auto gload = [&](int k0) {
#pragma unroll
        for (int p = 0; p < 2; p++) {
            int f = tid * 2 + p;
            int r = f >> 2, ch = f & 3;
            size_t offA = (size_t)(row0 + r) * lda + k0 + ch * 8;
            size_t offB = (size_t)(col0 + r) * ldb + k0 + ch * 8;
            rAh[p] = *(const uint4*)(Ah + offA);
            rAl[p] = *(const uint4*)(Al + offA);
            rBh[p] = *(const uint4*)(Bh + offB);
            rBl[p] = *(const uint4*)(Bl + offB);
        }
    };
    auto stage = [&]() {
#pragma unroll
        for (int p = 0; p < 2; p++) {
            int f = tid * 2 + p;
            int r = f >> 2, ch = f & 3;
            *(uint4*)&sA[0][r][ch * 8] = rAh[p];
            *(uint4*)&sA[1][r][ch * 8] = rAl[p];
            *(uint4*)&sB[0][r][ch * 8] = rBh[p];
            *(uint4*)&sB[1][r][ch * 8] = rBl[p];
        }
    };

    float acc[4][4][4] = {};   // [ar][bn][c-frag]

    gload(0);
    stage();
    __syncthreads();

    const int nstep = Ktot / BKC;
    for (int s = 0; s < nstep; s++) {
        bool more = (s + 1) < nstep;
        if (more) gload((s + 1) * BKC);
#pragma unroll
        for (int ks = 0; ks < BKC; ks += 16) {
            uint32_t fAh[4][4], fAl[4][4], fBh[4][2], fBl[4][2];
#pragma unroll
            for (int ar = 0; ar < 4; ar++) {
                int r0 = wm + ar * 16 + g;
                fAh[ar][0] = *(const uint32_t*)&sA[0][r0    ][ks + 2 * tig];
                fAh[ar][1] = *(const uint32_t*)&sA[0][r0 + 8][ks + 2 * tig];
                fAh[ar][2] = *(const uint32_t*)&sA[0][r0    ][ks + 2 * tig + 8];
                fAh[ar][3] = *(const uint32_t*)&sA[0][r0 + 8][ks + 2 * tig + 8];
                fAl[ar][0] = *(const uint32_t*)&sA[1][r0    ][ks + 2 * tig];
                fAl[ar][1] = *(const uint32_t*)&sA[1][r0 + 8][ks + 2 * tig];
                fAl[ar][2] = *(const uint32_t*)&sA[1][r0    ][ks + 2 * tig + 8];
                fAl[ar][3] = *(const uint32_t*)&sA[1][r0 + 8][ks + 2 * tig + 8];
            }
#pragma unroll
            for (int bn = 0; bn < 4; bn++) {
                int nr = wn + bn * 8 + g;
                fBh[bn][0] = *(const uint32_t*)&sB[0][nr][ks + 2 * tig];
                fBh[bn][1] = *(const uint32_t*)&sB[0][nr][ks + 2 * tig + 8];
                fBl[bn][0] = *(const uint32_t*)&sB[1][nr][ks + 2 * tig];
                fBl[bn][1] = *(const uint32_t*)&sB[1][nr][ks + 2 * tig + 8];
            }
#pragma unroll
            for (int ar = 0; ar < 4; ar++)
#pragma unroll
            for (int bn = 0; bn < 4; bn++) {
                mma16816(acc[ar][bn], fAh[ar][0], fAh[ar][1], fAh[ar][2], fAh[ar][3],
                         fBh[bn][0], fBh[bn][1]);
                mma16816(acc[ar][bn], fAh[ar][0], fAh[ar][1], fAh[ar][2], fAh[ar][3],
                         fBl[bn][0], fBl[bn][1]);
                mma16816(acc[ar][bn], fAl[ar][0], fAl[ar][1], fAl[ar][2], fAl[ar][3],
                         fBh[bn][0], fBh[bn][1]);
            }
        }
        if (more) {
            __syncthreads();
            stage();
            __syncthreads();
        }
    }

#pragma unroll
    for (int ar = 0; ar < 4; ar++) {
        int r0 = row0 + wm + ar * 16 + g;
#pragma unroll
        for (int bn = 0; bn < 4; bn++) {
            int c0 = col0 + wn + bn * 8 + 2 * tig;
            *(float2*)&C[(size_t)r0 * ldc + c0]       = make_float2(acc[ar][bn][0], acc[ar][bn][1]);
            *(float2*)&C[(size_t)(r0 + 8) * ldc + c0] = make_float2(acc[ar][bn][2], acc[ar][bn][3]);
        }
    }
}

// ---------------------------------------------------------------------------
// Row softmax; reads fp32 scores, writes split-bf16 attention.
// ---------------------------------------------------------------------------
__global__ void softmax_split(const float* __restrict__ S,
                              __nv_bfloat16* __restrict__ Ah,
                              __nv_bfloat16* __restrict__ Al) {
    __shared__ float red[256];
    const float4* p = (const float4*)(S + (size_t)blockIdx.x * NN);
    const int tid = threadIdx.x;

    float4 r[4];
    float mx = -INFINITY;
#pragma unroll
    for (int i = 0; i < 4; i++) {
        r[i] = p[tid + i * 256];
        mx = fmaxf(mx, fmaxf(fmaxf(r[i].x, r[i].y), fmaxf(r[i].z, r[i].w)));
    }
    red[tid] = mx;
    __syncthreads();
    for (int s = 128; s > 0; s >>= 1) {
        if (tid < s) red[tid] = fmaxf(red[tid], red[tid + s]);
        __syncthreads();
    }
    mx = red[0];
    __syncthreads();

    float sum = 0.0f;
#pragma unroll
    for (int i = 0; i < 4; i++) {
        r[i].x = __expf(r[i].x - mx); r[i].y = __expf(r[i].y - mx);
        r[i].z = __expf(r[i].z - mx); r[i].w = __expf(r[i].w - mx);
        sum += r[i].x + r[i].y + r[i].z + r[i].w;
    }
    red[tid] = sum;
    __syncthreads();
    for (int s = 128; s > 0; s >>= 1) {
        if (tid < s) red[tid] += red[tid + s];
        __syncthreads();
    }
    float inv = 1.0f / red[0];

    __nv_bfloat16* ah = Ah + (size_t)blockIdx.x * NN;
    __nv_bfloat16* al = Al + (size_t)blockIdx.x * NN;
#pragma unroll
    for (int i = 0; i < 4; i++) {
        float v[4] = {r[i].x * inv, r[i].y * inv, r[i].z * inv, r[i].w * inv};
        unsigned short hs[4], ls[4];
#pragma unroll
        for (int c = 0; c < 4; c++) split_bf16(v[c], hs[c], ls[c]);
        uint2 uh = make_uint2((uint32_t)hs[0] | ((uint32_t)hs[1] << 16),
                              (uint32_t)hs[2] | ((uint32_t)hs[3] << 16));
        uint2 ul = make_uint2((uint32_t)ls[0] | ((uint32_t)ls[1] << 16),
                              (uint32_t)ls[2] | ((uint32_t)ls[3] << 16));
        size_t off = (size_t)(tid + i * 256) * 4;
        *(uint2*)&ah[off] = uh;
        *(uint2*)&al[off] = ul;
    }
}

// ---------------------------------------------------------------------------
extern "C" void kernel_launch(void* const* d_in, const int* in_sizes, int n_in,
                              void* d_out, int out_size) {
    const float* x_q  = (const float*)d_in[0];
    const float* x_kv = (const float*)d_in[1];
    const float* Wq = (const float*)d_in[2];
    const float* bq = (const float*)d_in[3];
    const float* Wk = (const float*)d_in[4];
    const float* bk = (const float*)d_in[5];
    const float* Wv = (const float*)d_in[6];
    const float* bv = (const float*)d_in[7];
    const float* W1 = (const float*)d_in[8];
    const float* b1 = (const float*)d_in[9];
    const float* W2 = (const float*)d_in[10];
    const float* b2 = (const float*)d_in[11];
    float* out = (float*)d_out;

    __nv_bfloat16 *pqh, *pql, *pkh, *pkl, *pvh, *pvl, *pah, *pal;
    float *ps, *pav, *ph;
    cudaGetSymbolAddress((void**)&pqh, g_qh);
    cudaGetSymbolAddress((void**)&pql, g_ql);
    cudaGetSymbolAddress((void**)&pkh, g_kh);
    cudaGetSymbolAddress((void**)&pkl, g_kl);
    cudaGetSymbolAddress((void**)&pvh, g_vh);
    cudaGetSymbolAddress((void**)&pvl, g_vl);
    cudaGetSymbolAddress((void**)&ps,  g_s);
    cudaGetSymbolAddress((void**)&pah, g_ah);
    cudaGetSymbolAddress((void**)&pal, g_al);
    cudaGetSymbolAddress((void**)&pav, g_av);
    cudaGetSymbolAddress((void**)&ph,  g_hid);

    dim3 tb(256);
    dim3 gProj(NN / 128, CC / 128, BB);     // (32, 2, 4)
    dim3 gScore(NN / 128, NN / 128, BB);    // (32, 32, 4)
    dim3 gAV(NN / 128, CC / 128, BB);       // (32, 2, 4)

    // Projections with fused bf16 split epilogues
    gemm_wx<2, false><<<gProj, tb>>>(Wq, x_q,  bq, nullptr, pqh, pql);  // [n][c]
    gemm_wx<2, false><<<gProj, tb>>>(Wk, x_kv, bk, nullptr, pkh, pkl);  // [m][c]
    gemm_wx<1, false><<<gProj, tb>>>(Wv, x_kv, bv, nullptr, pvh, pvl);  // [c][m]

    // Scores: S[n][m] = sum_c Q'[n][c] K'[m][c]  (tensor cores, 3-term split)
    mma_gemm<<<gScore, tb>>>(pqh, pql, (size_t)NN * CC, CC,
                             pkh, pkl, (size_t)NN * CC, CC,
                             ps, (size_t)NN * NN, NN, CC);

    softmax_split<<<BB * NN, tb>>>(ps, pah, pal);

    // AV: av[c][n] = sum_m V[c][m] A[n][m]  (tensor cores, 3-term split)
    mma_gemm<<<gAV, tb>>>(pvh, pvl, (size_t)CC * NN, NN,
                          pah, pal, (size_t)NN * NN, NN,
                          pav, (size_t)CC * NN, NN, NN);

    // FFN (fp32)
    gemm_wx<0, true ><<<gProj, tb>>>(W1, pav, b1, ph,  nullptr, nullptr);
    gemm_wx<0, false><<<gProj, tb>>>(W2, ph,  b2, out, nullptr, nullptr);
}

// round 5
// speedup vs baseline: 2.2045x; 1.1437x over previous
#include <cuda_runtime.h>
#include <cuda_bf16.h>
#include <math.h>
#include <stddef.h>
#include <stdint.h>

#define BB 4
#define CC 256
#define NN 4096

// Scratch (__device__ globals; no allocation allowed)
__device__ __nv_bfloat16 g_qh[(size_t)BB * NN * CC];   // [b][n][c]
__device__ __nv_bfloat16 g_ql[(size_t)BB * NN * CC];
__device__ __nv_bfloat16 g_kh[(size_t)BB * NN * CC];   // [b][m][c]
__device__ __nv_bfloat16 g_kl[(size_t)BB * NN * CC];
__device__ __nv_bfloat16 g_vh[(size_t)BB * CC * NN];   // [b][c][m]
__device__ __nv_bfloat16 g_vl[(size_t)BB * CC * NN];
__device__ float         g_s [(size_t)BB * NN * NN];   // scores fp32 (256MB)
__device__ __nv_bfloat16 g_ah[(size_t)BB * NN * NN];   // attn hi [b][n][m]
__device__ __nv_bfloat16 g_al[(size_t)BB * NN * NN];   // attn lo
__device__ float         g_av[(size_t)BB * CC * NN];
__device__ float         g_hid[(size_t)BB * CC * NN];

// ---------------------------------------------------------------------------
// helpers
// ---------------------------------------------------------------------------
__device__ __forceinline__ void split_bf16(float f, unsigned short& h, unsigned short& l) {
    __nv_bfloat16 hb = __float2bfloat16(f);
    float r = f - __bfloat162float(hb);
    __nv_bfloat16 lb = __float2bfloat16(r);
    h = __bfloat16_as_ushort(hb);
    l = __bfloat16_as_ushort(lb);
}

__device__ __forceinline__ void mma16816(float c[4],
                                         const uint32_t a[4],
                                         uint32_t b0, uint32_t b1) {
    asm volatile(
        "mma.sync.aligned.m16n8k16.row.col.f32.bf16.bf16.f32 "
        "{%0,%1,%2,%3}, {%4,%5,%6,%7}, {%8,%9}, {%0,%1,%2,%3};"
        : "+f"(c[0]), "+f"(c[1]), "+f"(c[2]), "+f"(c[3])
        : "r"(a[0]), "r"(a[1]), "r"(a[2]), "r"(a[3]), "r"(b0), "r"(b1));
}

__device__ __forceinline__ void ldsm4(uint32_t r[4], uint32_t addr) {
    asm volatile("ldmatrix.sync.aligned.m8n8.x4.shared.b16 {%0,%1,%2,%3}, [%4];"
                 : "=r"(r[0]), "=r"(r[1]), "=r"(r[2]), "=r"(r[3]) : "r"(addr));
}

__device__ __forceinline__ void cp16(uint32_t dst, const void* src) {
    asm volatile("cp.async.cg.shared.global [%0], [%1], 16;" :: "r"(dst), "l"(src));
}

// ---------------------------------------------------------------------------
// Projection GEMM (fp32 mainloop) with selectable epilogue:
// MODE 0: fp32 out [b][o][n] (+bias, optional relu)
// MODE 1: split bf16 natural  [b][o][n] (V)
// MODE 2: split bf16 transposed [b][n][o] (Q, K)
// ---------------------------------------------------------------------------
#define BK 16
#define PAD 132

__device__ __forceinline__ void mm_step_f32(const float (*As)[PAD], const float (*Bs)[PAD],
                                            int kk, int ty, int tx, float acc[8][8]) {
    float4 a0 = *(const float4*)&As[kk][ty * 4];
    float4 a1 = *(const float4*)&As[kk][64 + ty * 4];
    float4 b0 = *(const float4*)&Bs[kk][tx * 4];
    float4 b1 = *(const float4*)&Bs[kk][64 + tx * 4];
    float a[8] = {a0.x, a0.y, a0.z, a0.w, a1.x, a1.y, a1.z, a1.w};
    float b[8] = {b0.x, b0.y, b0.z, b0.w, b1.x, b1.y, b1.z, b1.w};
#pragma unroll
    for (int i = 0; i < 8; i++)
#pragma unroll
        for (int j = 0; j < 8; j++) acc[i][j] = fmaf(a[i], b[j], acc[i][j]);
}

template <int MODE, bool RELU>
__global__ __launch_bounds__(256, 2)
void gemm_wx(const float* __restrict__ W, const float* __restrict__ X,
             const float* __restrict__ bias,
             float* __restrict__ outF,
             __nv_bfloat16* __restrict__ outH, __nv_bfloat16* __restrict__ outL) {
    __shared__ float Ws[2][BK][PAD];
    __shared__ float Xs[2][BK][PAD];

    const int b  = blockIdx.z;
    const int o0 = blockIdx.y * 128;
    const int n0 = blockIdx.x * 128;
    const float* Xb = X + (size_t)b * CC * NN;

    const int tid = threadIdx.x;
    const int tx  = tid & 15;
    const int ty  = tid >> 4;

    float4 wst[2], xst[2];

    auto loadTiles = [&](int k0) {
#pragma unroll
        for (int p = 0; p < 2; p++) {
            int f = tid * 2 + p;
            wst[p] = *(const float4*)&W[(size_t)(o0 + (f >> 2)) * CC + k0 + (f & 3) * 4];
            xst[p] = *(const float4*)&Xb[(size_t)(k0 + (f >> 5)) * NN + n0 + (f & 31) * 4];
        }
    };
    auto stage = [&](int s) {
#pragma unroll
        for (int p = 0; p < 2; p++) {
            int f = tid * 2 + p;
            int r = f >> 2, c4 = f & 3;
            Ws[s][c4 * 4 + 0][r] = wst[p].x;
            Ws[s][c4 * 4 + 1][r] = wst[p].y;
            Ws[s][c4 * 4 + 2][r] = wst[p].z;
            Ws[s][c4 * 4 + 3][r] = wst[p].w;
            *(float4*)&Xs[s][f >> 5][(f & 31) * 4] = xst[p];
        }
    };

    float acc[8][8] = {};

    loadTiles(0);
    stage(0);
    __syncthreads();

    const int NSTEP = CC / BK;
    for (int s = 0; s < NSTEP; s++) {
        int buf = s & 1;
        bool more = (s + 1) < NSTEP;
        if (more) loadTiles((s + 1) * BK);
#pragma unroll
        for (int kk = 0; kk < BK; kk++) mm_step_f32(Ws[buf], Xs[buf], kk, ty, tx, acc);
        if (more) {
            stage(buf ^ 1);
            __syncthreads();
        }
    }

    if (MODE == 0) {
        float* Ob = outF + (size_t)b * CC * NN;
#pragma unroll
        for (int h = 0; h < 2; h++)
#pragma unroll
        for (int r = 0; r < 4; r++) {
            int i = h * 4 + r;
            int o = o0 + h * 64 + ty * 4 + r;
            float bs = bias[o];
            float4 v0 = make_float4(acc[i][0] + bs, acc[i][1] + bs, acc[i][2] + bs, acc[i][3] + bs);
            float4 v1 = make_float4(acc[i][4] + bs, acc[i][5] + bs, acc[i][6] + bs, acc[i][7] + bs);
            if (RELU) {
                v0.x = fmaxf(v0.x, 0.f); v0.y = fmaxf(v0.y, 0.f); v0.z = fmaxf(v0.z, 0.f); v0.w = fmaxf(v0.w, 0.f);
                v1.x = fmaxf(v1.x, 0.f); v1.y = fmaxf(v1.y, 0.f); v1.z = fmaxf(v1.z, 0.f); v1.w = fmaxf(v1.w, 0.f);
            }
            *(float4*)&Ob[(size_t)o * NN + n0 + tx * 4]      = v0;
            *(float4*)&Ob[(size_t)o * NN + n0 + 64 + tx * 4] = v1;
        }
    } else if (MODE == 1) {
        __nv_bfloat16* Oh = outH + (size_t)b * CC * NN;
        __nv_bfloat16* Ol = outL + (size_t)b * CC * NN;
#pragma unroll
        for (int h = 0; h < 2; h++)
#pragma unroll
        for (int r = 0; r < 4; r++) {
            int i = h * 4 + r;
            int o = o0 + h * 64 + ty * 4 + r;
            float bs = bias[o];
#pragma unroll
            for (int gblk = 0; gblk < 2; gblk++) {
                unsigned short hs[4], ls[4];
#pragma unroll
                for (int cc = 0; cc < 4; cc++)
                    split_bf16(acc[i][gblk * 4 + cc] + bs, hs[cc], ls[cc]);
                uint2 uh = make_uint2((uint32_t)hs[0] | ((uint32_t)hs[1] << 16),
                                      (uint32_t)hs[2] | ((uint32_t)hs[3] << 16));
                uint2 ul = make_uint2((uint32_t)ls[0] | ((uint32_t)ls[1] << 16),
                                      (uint32_t)ls[2] | ((uint32_t)ls[3] << 16));
                size_t off = (size_t)o * NN + n0 + gblk * 64 + tx * 4;
                *(uint2*)&Oh[off] = uh;
                *(uint2*)&Ol[off] = ul;
            }
        }
    } else {
        __nv_bfloat16* Oh = outH + (size_t)b * NN * CC;
        __nv_bfloat16* Ol = outL + (size_t)b * NN * CC;
#pragma unroll
        for (int gblk = 0; gblk < 2; gblk++)
#pragma unroll
        for (int cc = 0; cc < 4; cc++) {
            int j = gblk * 4 + cc;
            int n = n0 + gblk * 64 + tx * 4 + cc;
#pragma unroll
            for (int h = 0; h < 2; h++) {
                int cbase = o0 + h * 64 + ty * 4;
                unsigned short hs[4], ls[4];
#pragma unroll
                for (int r = 0; r < 4; r++)
                    split_bf16(acc[h * 4 + r][j] + bias[cbase + r], hs[r], ls[r]);
                uint2 uh = make_uint2((uint32_t)hs[0] | ((uint32_t)hs[1] << 16),
                                      (uint32_t)hs[2] | ((uint32_t)hs[3] << 16));
                uint2 ul = make_uint2((uint32_t)ls[0] | ((uint32_t)ls[1] << 16),
                                      (uint32_t)ls[2] | ((uint32_t)ls[3] << 16));
                size_t off = (size_t)n * CC + cbase;
                *(uint2*)&Oh[off] = uh;
                *(uint2*)&Ol[off] = ul;
            }
        }
    }
}

// ---------------------------------------------------------------------------
// Tensor-core GEMM: C[row][col] = sum_k (Ah+Al)[row][k] * (Bh+Bl)[col][k]
// 3-term split. Block 128x128, BKC=32, 256 thr (warp tile 64x32).
// cp.async double-buffered, ldmatrix fragment loads.
// SMEM: [2 stage][2 hl][128][SPITCH] for A then B. 80KB dynamic.
// ---------------------------------------------------------------------------
#define BKC 32
#define SPITCH 40                       // elements; 80B pitch, conflict-free LDSM
#define ST_ELEMS (2 * 128 * SPITCH)     // per stage per operand (hl included)
#define ST_BYTES (ST_ELEMS * 2)         // 20480
#define B_OFF_BYTES (2 * ST_BYTES)      // 40960
#define SMEM_TOTAL_BYTES (4 * ST_BYTES) // 81920

extern __shared__ __align__(16) __nv_bfloat16 smem_mma[];

__global__ __launch_bounds__(256)
void mma_gemm(const __nv_bfloat16* __restrict__ Ah, const __nv_bfloat16* __restrict__ Al,
              size_t sAb, int lda,
              const __nv_bfloat16* __restrict__ Bh, const __nv_bfloat16* __restrict__ Bl,
              size_t sBb, int ldb,
              float* __restrict__ C, size_t sCb, int ldc, int Ktot) {
    const int b    = blockIdx.z;
    const int row0 = blockIdx.y * 128;
    const int col0 = blockIdx.x * 128;
    Ah += (size_t)b * sAb;  Al += (size_t)b * sAb;
    Bh += (size_t)b * sBb;  Bl += (size_t)b * sBb;
    C  += (size_t)b * sCb;

    const int tid  = threadIdx.x;
    const int w    = tid >> 5, lane = tid & 31;
    const int g    = lane >> 2, tig = lane & 3;
    const int wm   = (w & 1) * 64;
    const int wn   = (w >> 1) * 32;

    uint32_t smem_u32;
    asm("{ .reg .u64 t; cvta.to.shared.u64 t, %1; cvt.u32.u64 %0, t; }"
        : "=r"(smem_u32) : "l"(smem_mma));

    // copy one K-stage (A+B, hi+lo): 2048 16B chunks / 256 thr = 8 each
    auto issue_copy = [&](int k0, int st) {
#pragma unroll
        for (int i = 0; i < 8; i++) {
            int idx = tid + i * 256;
            int ab = idx >> 10;
            int h  = (idx >> 9) & 1;
            int r  = (idx >> 2) & 127;
            int ch = idx & 3;
            uint32_t dst = smem_u32 + st * ST_BYTES +
                           (uint32_t)(((h * 128 + r) * SPITCH + ch * 8) * 2);
            const __nv_bfloat16* src;
            if (ab == 0) {
                src = (h ? Al : Ah) + (size_t)(row0 + r) * lda + k0 + ch * 8;
            } else {
                dst += B_OFF_BYTES;
                src = (h ? Bl : Bh) + (size_t)(col0 + r) * ldb + k0 + ch * 8;
            }
            cp16(dst, src);
        }
        asm volatile("cp.async.commit_group;" ::: "memory");
    };

    float acc[4][4][4] = {};

    issue_copy(0, 0);
    asm volatile("cp.async.wait_group 0;" ::: "memory");
    __syncthreads();

    const int lr = lane & 15;            // row within 16-row ldsm block
    const int lc = (lane >> 4) * 8;      // k-offset 0 or 8

    const int nstep = Ktot / BKC;
    for (int s = 0; s < nstep; s++) {
        int st = s & 1;
        bool more = (s + 1) < nstep;
        if (more) issue_copy((s + 1) * BKC, st ^ 1);

        uint32_t aBase = smem_u32 + st * ST_BYTES;
        uint32_t bBase = aBase + B_OFF_BYTES;

#pragma unroll
        for (int ks = 0; ks < BKC; ks += 16) {
            uint32_t fA[2][4][4];   // [hl][ar][reg]
            uint32_t fB[2][2][4];   // [hl][bp][reg]
#pragma unroll
            for (int h = 0; h < 2; h++) {
#pragma unroll
                for (int ar = 0; ar < 4; ar++) {
                    uint32_t addr = aBase +
                        (uint32_t)(((h * 128 + wm + ar * 16 + lr) * SPITCH + ks + lc) * 2);
                    ldsm4(fA[h][ar], addr);
                }
#pragma unroll
                for (int bp = 0; bp < 2; bp++) {
                    uint32_t addr = bBase +
                        (uint32_t)(((h * 128 + wn + bp * 16 + lr) * SPITCH + ks + lc) * 2);
                    ldsm4(fB[h][bp], addr);
                }
            }
#pragma unroll
            for (int ar = 0; ar < 4; ar++)
#pragma unroll
            for (int bn = 0; bn < 4; bn++) {
                int bp = bn >> 1, sel = bn & 1;
                uint32_t b0h = fB[0][bp][sel],     b1h = fB[0][bp][2 + sel];
                uint32_t b0l = fB[1][bp][sel],     b1l = fB[1][bp][2 + sel];
                mma16816(acc[ar][bn], fA[0][ar], b0h, b1h);   // hh
                mma16816(acc[ar][bn], fA[0][ar], b0l, b1l);   // hl
                mma16816(acc[ar][bn], fA[1][ar], b0h, b1h);   // lh
            }
        }
        if (more) {
            asm volatile("cp.async.wait_group 0;" ::: "memory");
            __syncthreads();
        }
    }

#pragma unroll
    for (int ar = 0; ar < 4; ar++) {
        int r0 = row0 + wm + ar * 16 + g;
#pragma unroll
        for (int bn = 0; bn < 4; bn++) {
            int c0 = col0 + wn + bn * 8 + 2 * tig;
            *(float2*)&C[(size_t)r0 * ldc + c0]       = make_float2(acc[ar][bn][0], acc[ar][bn][1]);
            *(float2*)&C[(size_t)(r0 + 8) * ldc + c0] = make_float2(acc[ar][bn][2], acc[ar][bn][3]);
        }
    }
}

// ---------------------------------------------------------------------------
// Row softmax; reads fp32 scores, writes split-bf16 attention.
// ---------------------------------------------------------------------------
__global__ void softmax_split(const float* __restrict__ S,
                              __nv_bfloat16* __restrict__ Ah,
                              __nv_bfloat16* __restrict__ Al) {
    __shared__ float red[256];
    const float4* p = (const float4*)(S + (size_t)blockIdx.x * NN);
    const int tid = threadIdx.x;

    float4 r[4];
    float mx = -INFINITY;
#pragma unroll
    for (int i = 0; i < 4; i++) {
        r[i] = p[tid + i * 256];
        mx = fmaxf(mx, fmaxf(fmaxf(r[i].x, r[i].y), fmaxf(r[i].z, r[i].w)));
    }
    red[tid] = mx;
    __syncthreads();
    for (int s = 128; s > 0; s >>= 1) {
        if (tid < s) red[tid] = fmaxf(red[tid], red[tid + s]);
        __syncthreads();
    }
    mx = red[0];
    __syncthreads();

    float sum = 0.0f;
#pragma unroll
    for (int i = 0; i < 4; i++) {
        r[i].x = __expf(r[i].x - mx); r[i].y = __expf(r[i].y - mx);
        r[i].z = __expf(r[i].z - mx); r[i].w = __expf(r[i].w - mx);
        sum += r[i].x + r[i].y + r[i].z + r[i].w;
    }
    red[tid] = sum;
    __syncthreads();
    for (int s = 128; s > 0; s >>= 1) {
        if (tid < s) red[tid] += red[tid + s];
        __syncthreads();
    }
    float inv = 1.0f / red[0];

    __nv_bfloat16* ah = Ah + (size_t)blockIdx.x * NN;
    __nv_bfloat16* al = Al + (size_t)blockIdx.x * NN;
#pragma unroll
    for (int i = 0; i < 4; i++) {
        float v[4] = {r[i].x * inv, r[i].y * inv, r[i].z * inv, r[i].w * inv};
        unsigned short hs[4], ls[4];
#pragma unroll
        for (int c = 0; c < 4; c++) split_bf16(v[c], hs[c], ls[c]);
        uint2 uh = make_uint2((uint32_t)hs[0] | ((uint32_t)hs[1] << 16),
                              (uint32_t)hs[2] | ((uint32_t)hs[3] << 16));
        uint2 ul = make_uint2((uint32_t)ls[0] | ((uint32_t)ls[1] << 16),
                              (uint32_t)ls[2] | ((uint32_t)ls[3] << 16));
        size_t off = (size_t)(tid + i * 256) * 4;
        *(uint2*)&ah[off] = uh;
        *(uint2*)&al[off] = ul;
    }
}

// ---------------------------------------------------------------------------
extern "C" void kernel_launch(void* const* d_in, const int* in_sizes, int n_in,
                              void* d_out, int out_size) {
    const float* x_q  = (const float*)d_in[0];
    const float* x_kv = (const float*)d_in[1];
    const float* Wq = (const float*)d_in[2];
    const float* bq = (const float*)d_in[3];
    const float* Wk = (const float*)d_in[4];
    const float* bk = (const float*)d_in[5];
    const float* Wv = (const float*)d_in[6];
    const float* bv = (const float*)d_in[7];
    const float* W1 = (const float*)d_in[8];
    const float* b1 = (const float*)d_in[9];
    const float* W2 = (const float*)d_in[10];
    const float* b2 = (const float*)d_in[11];
    float* out = (float*)d_out;

    __nv_bfloat16 *pqh, *pql, *pkh, *pkl, *pvh, *pvl, *pah, *pal;
    float *ps, *pav, *ph;
    cudaGetSymbolAddress((void**)&pqh, g_qh);
    cudaGetSymbolAddress((void**)&pql, g_ql);
    cudaGetSymbolAddress((void**)&pkh, g_kh);
    cudaGetSymbolAddress((void**)&pkl, g_kl);
    cudaGetSymbolAddress((void**)&pvh, g_vh);
    cudaGetSymbolAddress((void**)&pvl, g_vl);
    cudaGetSymbolAddress((void**)&ps,  g_s);
    cudaGetSymbolAddress((void**)&pah, g_ah);
    cudaGetSymbolAddress((void**)&pal, g_al);
    cudaGetSymbolAddress((void**)&pav, g_av);
    cudaGetSymbolAddress((void**)&ph,  g_hid);

    // allow 80KB dynamic smem for mma_gemm (idempotent; no allocation)
    cudaFuncSetAttribute(mma_gemm, cudaFuncAttributeMaxDynamicSharedMemorySize,
                         SMEM_TOTAL_BYTES);

    dim3 tb(256);
    dim3 gProj(NN / 128, CC / 128, BB);     // (32, 2, 4)
    dim3 gScore(NN / 128, NN / 128, BB);    // (32, 32, 4)
    dim3 gAV(NN / 128, CC / 128, BB);       // (32, 2, 4)

    gemm_wx<2, false><<<gProj, tb>>>(Wq, x_q,  bq, nullptr, pqh, pql);  // [n][c]
    gemm_wx<2, false><<<gProj, tb>>>(Wk, x_kv, bk, nullptr, pkh, pkl);  // [m][c]
    gemm_wx<1, false><<<gProj, tb>>>(Wv, x_kv, bv, nullptr, pvh, pvl);  // [c][m]

    mma_gemm<<<gScore, tb, SMEM_TOTAL_BYTES>>>(pqh, pql, (size_t)NN * CC, CC,
                                               pkh, pkl, (size_t)NN * CC, CC,
                                               ps, (size_t)NN * NN, NN, CC);

    softmax_split<<<BB * NN, tb>>>(ps, pah, pal);

    mma_gemm<<<gAV, tb, SMEM_TOTAL_BYTES>>>(pvh, pvl, (size_t)CC * NN, NN,
                                            pah, pal, (size_t)NN * NN, NN,
                                            pav, (size_t)CC * NN, NN, NN);

    gemm_wx<0, true ><<<gProj, tb>>>(W1, pav, b1, ph,  nullptr, nullptr);
    gemm_wx<0, false><<<gProj, tb>>>(W2, ph,  b2, out, nullptr, nullptr);
}

// round 6
// speedup vs baseline: 2.4075x; 1.0921x over previous
#include <cuda_runtime.h>
#include <cuda_bf16.h>
#include <math.h>
#include <stddef.h>
#include <stdint.h>

#define BB 4
#define CC 256
#define NN 4096

typedef __nv_bfloat16 bf16;

// ---------------------------------------------------------------------------
// Scratch (__device__ globals; no allocation allowed)
// ---------------------------------------------------------------------------
__device__ __align__(16) bf16 g_xqt_h[(size_t)BB * NN * CC];  // x_q^T  [b][n][c]
__device__ __align__(16) bf16 g_xqt_l[(size_t)BB * NN * CC];
__device__ __align__(16) bf16 g_xkt_h[(size_t)BB * NN * CC];  // x_kv^T [b][n][c]
__device__ __align__(16) bf16 g_xkt_l[(size_t)BB * NN * CC];
__device__ __align__(16) bf16 g_w_h[5 * CC * CC];             // Wq,Wk,Wv,W1,W2 split
__device__ __align__(16) bf16 g_w_l[5 * CC * CC];
__device__ __align__(16) bf16 g_qt_h[(size_t)BB * NN * CC];   // q^T [b][n][c]
__device__ __align__(16) bf16 g_qt_l[(size_t)BB * NN * CC];
__device__ __align__(16) bf16 g_kt_h[(size_t)BB * NN * CC];   // k^T [b][m][c]
__device__ __align__(16) bf16 g_kt_l[(size_t)BB * NN * CC];
__device__ __align__(16) bf16 g_v_h[(size_t)BB * CC * NN];    // v   [b][c][m]
__device__ __align__(16) bf16 g_v_l[(size_t)BB * CC * NN];
__device__ __align__(16) float g_s[(size_t)BB * NN * NN];     // scores fp32 (256MB)
__device__ __align__(16) bf16 g_ah[(size_t)BB * NN * NN];     // attn hi [b][n][m]
__device__ __align__(16) bf16 g_al[(size_t)BB * NN * NN];
__device__ __align__(16) bf16 g_avt_h[(size_t)BB * NN * CC];  // av^T [b][n][c]
__device__ __align__(16) bf16 g_avt_l[(size_t)BB * NN * CC];
__device__ __align__(16) bf16 g_ht_h[(size_t)BB * NN * CC];   // hid^T [b][n][c]
__device__ __align__(16) bf16 g_ht_l[(size_t)BB * NN * CC];

// ---------------------------------------------------------------------------
// helpers
// ---------------------------------------------------------------------------
__device__ __forceinline__ void split_bf16(float f, unsigned short& h, unsigned short& l) {
    bf16 hb = __float2bfloat16(f);
    float r = f - __bfloat162float(hb);
    bf16 lb = __float2bfloat16(r);
    h = __bfloat16_as_ushort(hb);
    l = __bfloat16_as_ushort(lb);
}

__device__ __forceinline__ void mma16816(float c[4],
                                         const uint32_t a[4],
                                         uint32_t b0, uint32_t b1) {
    asm volatile(
        "mma.sync.aligned.m16n8k16.row.col.f32.bf16.bf16.f32 "
        "{%0,%1,%2,%3}, {%4,%5,%6,%7}, {%8,%9}, {%0,%1,%2,%3};"
        : "+f"(c[0]), "+f"(c[1]), "+f"(c[2]), "+f"(c[3])
        : "r"(a[0]), "r"(a[1]), "r"(a[2]), "r"(a[3]), "r"(b0), "r"(b1));
}

__device__ __forceinline__ void ldsm4(uint32_t r[4], uint32_t addr) {
    asm volatile("ldmatrix.sync.aligned.m8n8.x4.shared.b16 {%0,%1,%2,%3}, [%4];"
                 : "=r"(r[0]), "=r"(r[1]), "=r"(r[2]), "=r"(r[3]) : "r"(addr));
}

__device__ __forceinline__ void cp16(uint32_t dst, const void* src) {
    asm volatile("cp.async.cg.shared.global [%0], [%1], 16;" :: "r"(dst), "l"(src));
}

// ---------------------------------------------------------------------------
// split-transpose: X [b][c][n] fp32 -> T [b][n][c] bf16 hi/lo
// ---------------------------------------------------------------------------
__global__ void split_transpose(const float* __restrict__ X,
                                unsigned short* __restrict__ Th,
                                unsigned short* __restrict__ Tl) {
    __shared__ float tile[32][33];
    const int b  = blockIdx.z;
    const int c0 = blockIdx.y * 32;
    const int n0 = blockIdx.x * 32;
    const float* Xb = X + (size_t)b * CC * NN;
    const int tx = threadIdx.x, ty = threadIdx.y;

#pragma unroll
    for (int i = 0; i < 4; i++)
        tile[ty + 8 * i][tx] = Xb[(size_t)(c0 + ty + 8 * i) * NN + n0 + tx];
    __syncthreads();

    unsigned short* Thb = Th + (size_t)b * NN * CC;
    unsigned short* Tlb = Tl + (size_t)b * NN * CC;
#pragma unroll
    for (int i = 0; i < 4; i++) {
        float v = tile[tx][ty + 8 * i];
        unsigned short h, l;
        split_bf16(v, h, l);
        size_t off = (size_t)(n0 + ty + 8 * i) * CC + c0 + tx;
        Thb[off] = h;
        Tlb[off] = l;
    }
}

// ---------------------------------------------------------------------------
// plain split: W fp32 -> hi/lo (same layout)
// ---------------------------------------------------------------------------
__global__ void split_mat(const float* __restrict__ W,
                          unsigned short* __restrict__ Wh,
                          unsigned short* __restrict__ Wl, int n) {
    int i = blockIdx.x * blockDim.x + threadIdx.x;
    if (i < n) {
        unsigned short h, l;
        split_bf16(W[i], h, l);
        Wh[i] = h;
        Wl[i] = l;
    }
}

// ---------------------------------------------------------------------------
// Tensor-core GEMM: C[row][col] = sum_k (Ah+Al)[row][k]*(Bh+Bl)[col][k] (+bias)
// 3-term split. Block 128x128, BKC=32, 256 thr (warp tile 64x32).
// Epilogues: EPI 0 = fp32 natural [row][col]
//            EPI 1 = split bf16 natural [row][col]
//            EPI 2 = split bf16 transposed [col][row]
// ---------------------------------------------------------------------------
#define BKC 32
#define SPITCH 40
#define ST_ELEMS (2 * 128 * SPITCH)
#define ST_BYTES (ST_ELEMS * 2)          // 20480
#define B_OFF_BYTES (2 * ST_BYTES)       // 40960
#define SMEM_TOTAL_BYTES (4 * ST_BYTES)  // 81920

extern __shared__ __align__(16) bf16 smem_mma[];

template <int EPI, bool RELU>
__global__ __launch_bounds__(256)
void mma_gemm(const bf16* __restrict__ Ah, const bf16* __restrict__ Al,
              size_t sAb, int lda,
              const bf16* __restrict__ Bh, const bf16* __restrict__ Bl,
              size_t sBb, int ldb,
              float* __restrict__ Cf,
              unsigned short* __restrict__ Ch, unsigned short* __restrict__ Cl,
              size_t sCb, int ldc,
              const float* __restrict__ bias, int Ktot) {
    const int b    = blockIdx.z;
    const int row0 = blockIdx.y * 128;
    const int col0 = blockIdx.x * 128;
    Ah += (size_t)b * sAb;  Al += (size_t)b * sAb;
    Bh += (size_t)b * sBb;  Bl += (size_t)b * sBb;

    const int tid  = threadIdx.x;
    const int w    = tid >> 5, lane = tid & 31;
    const int g    = lane >> 2, tig = lane & 3;
    const int wm   = (w & 1) * 64;
    const int wn   = (w >> 1) * 32;

    uint32_t smem_u32;
    asm("{ .reg .u64 t; cvta.to.shared.u64 t, %1; cvt.u32.u64 %0, t; }"
        : "=r"(smem_u32) : "l"(smem_mma));

    auto issue_copy = [&](int k0, int st) {
#pragma unroll
        for (int i = 0; i < 8; i++) {
            int idx = tid + i * 256;
            int ab = idx >> 10;
            int h  = (idx >> 9) & 1;
            int r  = (idx >> 2) & 127;
            int ch = idx & 3;
            uint32_t dst = smem_u32 + st * ST_BYTES +
                           (uint32_t)(((h * 128 + r) * SPITCH + ch * 8) * 2);
            const bf16* src;
            if (ab == 0) {
                src = (h ? Al : Ah) + (size_t)(row0 + r) * lda + k0 + ch * 8;
            } else {
                dst += B_OFF_BYTES;
                src = (h ? Bl : Bh) + (size_t)(col0 + r) * ldb + k0 + ch * 8;
            }
            cp16(dst, src);
        }
        asm volatile("cp.async.commit_group;" ::: "memory");
    };

    float acc[4][4][4] = {};

    issue_copy(0, 0);
    asm volatile("cp.async.wait_group 0;" ::: "memory");
    __syncthreads();

    const int lr = lane & 15;
    const int lc = (lane >> 4) * 8;

    const int nstep = Ktot / BKC;
    for (int s = 0; s < nstep; s++) {
        int st = s & 1;
        bool more = (s + 1) < nstep;
        if (more) issue_copy((s + 1) * BKC, st ^ 1);

        uint32_t aBase = smem_u32 + st * ST_BYTES;
        uint32_t bBase = aBase + B_OFF_BYTES;

#pragma unroll
        for (int ks = 0; ks < BKC; ks += 16) {
            uint32_t fA[2][4][4];
            uint32_t fB[2][2][4];
#pragma unroll
            for (int h = 0; h < 2; h++) {
#pragma unroll
                for (int ar = 0; ar < 4; ar++) {
                    uint32_t addr = aBase +
                        (uint32_t)(((h * 128 + wm + ar * 16 + lr) * SPITCH + ks + lc) * 2);
                    ldsm4(fA[h][ar], addr);
                }
#pragma unroll
                for (int bp = 0; bp < 2; bp++) {
                    uint32_t addr = bBase +
                        (uint32_t)(((h * 128 + wn + bp * 16 + lr) * SPITCH + ks + lc) * 2);
                    ldsm4(fB[h][bp], addr);
                }
            }
#pragma unroll
            for (int ar = 0; ar < 4; ar++)
#pragma unroll
            for (int bn = 0; bn < 4; bn++) {
                int bp = bn >> 1, sel = bn & 1;
                uint32_t b0h = fB[0][bp][sel], b1h = fB[0][bp][2 + sel];
                uint32_t b0l = fB[1][bp][sel], b1l = fB[1][bp][2 + sel];
                mma16816(acc[ar][bn], fA[0][ar], b0h, b1h);   // hh
                mma16816(acc[ar][bn], fA[0][ar], b0l, b1l);   // hl
                mma16816(acc[ar][bn], fA[1][ar], b0h, b1h);   // lh
            }
        }
        if (more) {
            asm volatile("cp.async.wait_group 0;" ::: "memory");
            __syncthreads();
        }
    }

    // ---------------- epilogues ----------------
#pragma unroll
    for (int ar = 0; ar < 4; ar++) {
        int r0 = row0 + wm + ar * 16 + g;
        float bs0 = bias ? bias[r0]     : 0.0f;
        float bs8 = bias ? bias[r0 + 8] : 0.0f;
#pragma unroll
        for (int bn = 0; bn < 4; bn++) {
            int c0 = col0 + wn + bn * 8 + 2 * tig;
            float v0 = acc[ar][bn][0] + bs0;
            float v1 = acc[ar][bn][1] + bs0;
            float v2 = acc[ar][bn][2] + bs8;
            float v3 = acc[ar][bn][3] + bs8;
            if (RELU) {
                v0 = fmaxf(v0, 0.f); v1 = fmaxf(v1, 0.f);
                v2 = fmaxf(v2, 0.f); v3 = fmaxf(v3, 0.f);
            }
            if (EPI == 0) {
                float* C = Cf + (size_t)b * sCb;
                *(float2*)&C[(size_t)r0 * ldc + c0]       = make_float2(v0, v1);
                *(float2*)&C[(size_t)(r0 + 8) * ldc + c0] = make_float2(v2, v3);
            } else if (EPI == 1) {
                unsigned short* Hc = Ch + (size_t)b * sCb;
                unsigned short* Lc = Cl + (size_t)b * sCb;
                unsigned short h0, l0, h1, l1, h2, l2, h3, l3;
                split_bf16(v0, h0, l0); split_bf16(v1, h1, l1);
                split_bf16(v2, h2, l2); split_bf16(v3, h3, l3);
                *(uint32_t*)&Hc[(size_t)r0 * ldc + c0]       = (uint32_t)h0 | ((uint32_t)h1 << 16);
                *(uint32_t*)&Lc[(size_t)r0 * ldc + c0]       = (uint32_t)l0 | ((uint32_t)l1 << 16);
                *(uint32_t*)&Hc[(size_t)(r0 + 8) * ldc + c0] = (uint32_t)h2 | ((uint32_t)h3 << 16);
                *(uint32_t*)&Lc[(size_t)(r0 + 8) * ldc + c0] = (uint32_t)l2 | ((uint32_t)l3 << 16);
            } else {
                unsigned short* Hc = Ch + (size_t)b * sCb;
                unsigned short* Lc = Cl + (size_t)b * sCb;
                unsigned short h, l;
                split_bf16(v0, h, l);
                Hc[(size_t)c0 * ldc + r0] = h;           Lc[(size_t)c0 * ldc + r0] = l;
                split_bf16(v1, h, l);
                Hc[(size_t)(c0 + 1) * ldc + r0] = h;     Lc[(size_t)(c0 + 1) * ldc + r0] = l;
                split_bf16(v2, h, l);
                Hc[(size_t)c0 * ldc + r0 + 8] = h;       Lc[(size_t)c0 * ldc + r0 + 8] = l;
                split_bf16(v3, h, l);
                Hc[(size_t)(c0 + 1) * ldc + r0 + 8] = h; Lc[(size_t)(c0 + 1) * ldc + r0 + 8] = l;
            }
        }
    }
}

// ---------------------------------------------------------------------------
// Row softmax; reads fp32 scores, writes split-bf16 attention.
// ---------------------------------------------------------------------------
__global__ void softmax_split(const float* __restrict__ S,
                              bf16* __restrict__ Ah, bf16* __restrict__ Al) {
    __shared__ float red[256];
    const float4* p = (const float4*)(S + (size_t)blockIdx.x * NN);
    const int tid = threadIdx.x;

    float4 r[4];
    float mx = -INFINITY;
#pragma unroll
    for (int i = 0; i < 4; i++) {
        r[i] = p[tid + i * 256];
        mx = fmaxf(mx, fmaxf(fmaxf(r[i].x, r[i].y), fmaxf(r[i].z, r[i].w)));
    }
    red[tid] = mx;
    __syncthreads();
    for (int s = 128; s > 0; s >>= 1) {
        if (tid < s) red[tid] = fmaxf(red[tid], red[tid + s]);
        __syncthreads();
    }
    mx = red[0];
    __syncthreads();

    float sum = 0.0f;
#pragma unroll
    for (int i = 0; i < 4; i++) {
        r[i].x = __expf(r[i].x - mx); r[i].y = __expf(r[i].y - mx);
        r[i].z = __expf(r[i].z - mx); r[i].w = __expf(r[i].w - mx);
        sum += r[i].x + r[i].y + r[i].z + r[i].w;
    }
    red[tid] = sum;
    __syncthreads();
    for (int s = 128; s > 0; s >>= 1) {
        if (tid < s) red[tid] += red[tid + s];
        __syncthreads();
    }
    float inv = 1.0f / red[0];

    bf16* ah = Ah + (size_t)blockIdx.x * NN;
    bf16* al = Al + (size_t)blockIdx.x * NN;
#pragma unroll
    for (int i = 0; i < 4; i++) {
        float v[4] = {r[i].x * inv, r[i].y * inv, r[i].z * inv, r[i].w * inv};
        unsigned short hs[4], ls[4];
#pragma unroll
        for (int c = 0; c < 4; c++) split_bf16(v[c], hs[c], ls[c]);
        uint2 uh = make_uint2((uint32_t)hs[0] | ((uint32_t)hs[1] << 16),
                              (uint32_t)hs[2] | ((uint32_t)hs[3] << 16));
        uint2 ul = make_uint2((uint32_t)ls[0] | ((uint32_t)ls[1] << 16),
                              (uint32_t)ls[2] | ((uint32_t)ls[3] << 16));
        size_t off = (size_t)(tid + i * 256) * 4;
        *(uint2*)&ah[off] = uh;
        *(uint2*)&al[off] = ul;
    }
}

// ---------------------------------------------------------------------------
extern "C" void kernel_launch(void* const* d_in, const int* in_sizes, int n_in,
                              void* d_out, int out_size) {
    const float* x_q  = (const float*)d_in[0];
    const float* x_kv = (const float*)d_in[1];
    const float* Wq = (const float*)d_in[2];
    const float* bq = (const float*)d_in[3];
    const float* Wk = (const float*)d_in[4];
    const float* bk = (const float*)d_in[5];
    const float* Wv = (const float*)d_in[6];
    const float* bv = (const float*)d_in[7];
    const float* W1 = (const float*)d_in[8];
    const float* b1 = (const float*)d_in[9];
    const float* W2 = (const float*)d_in[10];
    const float* b2 = (const float*)d_in[11];
    float* out = (float*)d_out;

    bf16 *xqt_h, *xqt_l, *xkt_h, *xkt_l, *w_h, *w_l;
    bf16 *qt_h, *qt_l, *kt_h, *kt_l, *v_h, *v_l;
    bf16 *ah, *al, *avt_h, *avt_l, *ht_h, *ht_l;
    float* ps;
    cudaGetSymbolAddress((void**)&xqt_h, g_xqt_h);
    cudaGetSymbolAddress((void**)&xqt_l, g_xqt_l);
    cudaGetSymbolAddress((void**)&xkt_h, g_xkt_h);
    cudaGetSymbolAddress((void**)&xkt_l, g_xkt_l);
    cudaGetSymbolAddress((void**)&w_h,   g_w_h);
    cudaGetSymbolAddress((void**)&w_l,   g_w_l);
    cudaGetSymbolAddress((void**)&qt_h,  g_qt_h);
    cudaGetSymbolAddress((void**)&qt_l,  g_qt_l);
    cudaGetSymbolAddress((void**)&kt_h,  g_kt_h);
    cudaGetSymbolAddress((void**)&kt_l,  g_kt_l);
    cudaGetSymbolAddress((void**)&v_h,   g_v_h);
    cudaGetSymbolAddress((void**)&v_l,   g_v_l);
    cudaGetSymbolAddress((void**)&ps,    g_s);
    cudaGetSymbolAddress((void**)&ah,    g_ah);
    cudaGetSymbolAddress((void**)&al,    g_al);
    cudaGetSymbolAddress((void**)&avt_h, g_avt_h);
    cudaGetSymbolAddress((void**)&avt_l, g_avt_l);
    cudaGetSymbolAddress((void**)&ht_h,  g_ht_h);
    cudaGetSymbolAddress((void**)&ht_l,  g_ht_l);

    cudaFuncSetAttribute(mma_gemm<0, false>, cudaFuncAttributeMaxDynamicSharedMemorySize, SMEM_TOTAL_BYTES);
    cudaFuncSetAttribute(mma_gemm<1, false>, cudaFuncAttributeMaxDynamicSharedMemorySize, SMEM_TOTAL_BYTES);
    cudaFuncSetAttribute(mma_gemm<2, false>, cudaFuncAttributeMaxDynamicSharedMemorySize, SMEM_TOTAL_BYTES);
    cudaFuncSetAttribute(mma_gemm<2, true>,  cudaFuncAttributeMaxDynamicSharedMemorySize, SMEM_TOTAL_BYTES);

    const int WSZ = CC * CC;

    dim3 tb(256);
    dim3 gT(NN / 32, CC / 32, BB);          // split-transpose
    dim3 gProj(NN / 128, CC / 128, BB);     // (32, 2, 4)
    dim3 gScore(NN / 128, NN / 128, BB);    // (32, 32, 4)

    // 1. input split-transpose + weight splits
    split_transpose<<<gT, dim3(32, 8)>>>(x_q,  (unsigned short*)xqt_h, (unsigned short*)xqt_l);
    split_transpose<<<gT, dim3(32, 8)>>>(x_kv, (unsigned short*)xkt_h, (unsigned short*)xkt_l);
    split_mat<<<WSZ / 256, 256>>>(Wq, (unsigned short*)(w_h + 0 * WSZ), (unsigned short*)(w_l + 0 * WSZ), WSZ);
    split_mat<<<WSZ / 256, 256>>>(Wk, (unsigned short*)(w_h + 1 * WSZ), (unsigned short*)(w_l + 1 * WSZ), WSZ);
    split_mat<<<WSZ / 256, 256>>>(Wv, (unsigned short*)(w_h + 2 * WSZ), (unsigned short*)(w_l + 2 * WSZ), WSZ);
    split_mat<<<WSZ / 256, 256>>>(W1, (unsigned short*)(w_h + 3 * WSZ), (unsigned short*)(w_l + 3 * WSZ), WSZ);
    split_mat<<<WSZ / 256, 256>>>(W2, (unsigned short*)(w_h + 4 * WSZ), (unsigned short*)(w_l + 4 * WSZ), WSZ);

    // 2. projections on tensor cores
    // Q: C[o][n] -> transposed split q_t[n][o]
    mma_gemm<2, false><<<gProj, tb, SMEM_TOTAL_BYTES>>>(
        w_h + 0 * WSZ, w_l + 0 * WSZ, 0, CC,
        xqt_h, xqt_l, (size_t)NN * CC, CC,
        nullptr, (unsigned short*)qt_h, (unsigned short*)qt_l,
        (size_t)NN * CC, CC, bq, CC);
    mma_gemm<2, false><<<gProj, tb, SMEM_TOTAL_BYTES>>>(
        w_h + 1 * WSZ, w_l + 1 * WSZ, 0, CC,
        xkt_h, xkt_l, (size_t)NN * CC, CC,
        nullptr, (unsigned short*)kt_h, (unsigned short*)kt_l,
        (size_t)NN * CC, CC, bk, CC);
    // V: natural split v[c][m]
    mma_gemm<1, false><<<gProj, tb, SMEM_TOTAL_BYTES>>>(
        w_h + 2 * WSZ, w_l + 2 * WSZ, 0, CC,
        xkt_h, xkt_l, (size_t)NN * CC, CC,
        nullptr, (unsigned short*)v_h, (unsigned short*)v_l,
        (size_t)CC * NN, NN, bv, CC);

    // 3. scores S[n][m] fp32
    mma_gemm<0, false><<<gScore, tb, SMEM_TOTAL_BYTES>>>(
        qt_h, qt_l, (size_t)NN * CC, CC,
        kt_h, kt_l, (size_t)NN * CC, CC,
        ps, nullptr, nullptr, (size_t)NN * NN, NN, nullptr, CC);

    // 4. softmax -> split attn
    softmax_split<<<BB * NN, tb>>>(ps, ah, al);

    // 5. AV: C[c][n] -> transposed split av_t[n][c]
    mma_gemm<2, false><<<gProj, tb, SMEM_TOTAL_BYTES>>>(
        v_h, v_l, (size_t)CC * NN, NN,
        ah, al, (size_t)NN * NN, NN,
        nullptr, (unsigned short*)avt_h, (unsigned short*)avt_l,
        (size_t)NN * CC, CC, nullptr, NN);

    // 6. FFN1 (relu fused): C[o][n] -> transposed split hid_t[n][o]
    mma_gemm<2, true><<<gProj, tb, SMEM_TOTAL_BYTES>>>(
        w_h + 3 * WSZ, w_l + 3 * WSZ, 0, CC,
        avt_h, avt_l, (size_t)NN * CC, CC,
        nullptr, (unsigned short*)ht_h, (unsigned short*)ht_l,
        (size_t)NN * CC, CC, b1, CC);

    // 7. FFN2: fp32 out [o][n]
    mma_gemm<0, false><<<gProj, tb, SMEM_TOTAL_BYTES>>>(
        w_h + 4 * WSZ, w_l + 4 * WSZ, 0, CC,
        ht_h, ht_l, (size_t)NN * CC, CC,
        out, nullptr, nullptr, (size_t)CC * NN, NN, b2, CC);
}